// round 7
// baseline (speedup 1.0000x reference)
#include <cuda_runtime.h>
#include <cstdint>

// RVQ fused fp32 kernel, FFMA2 with zero-MOV operand feeding.
// Transposed activations in smem; diag/anti pair accumulation; swapped-copy tiles.
// B=65536, C=1024, D=256, K=2048, 4 codebooks. CTA = 32 rows, 256 threads, occ 1.

constexpr int Bn  = 65536;
constexpr int Cc  = 1024;
constexpr int Dd  = 256;
constexpr int Kk  = 2048;
constexpr int NCB = 4;
constexpr int BR  = 32;
constexpr int NT  = 256;
constexpr int CBT = 132;   // padded code stride for phase-B cbT tiles

typedef unsigned long long ull;

__device__ double g_loss_acc;
__device__ __align__(16) float g_c2[NCB * Kk];

__device__ __forceinline__ void upk2(ull v, float& lo, float& hi) {
    asm("mov.b64 {%0, %1}, %2;" : "=f"(lo), "=f"(hi) : "l"(v));
}
__device__ __forceinline__ void ffma2(ull& acc, ull a, ull b) {
    asm("fma.rn.f32x2 %0, %1, %2, %3;" : "=l"(acc) : "l"(a), "l"(b), "l"(acc));
}
__device__ __forceinline__ void cp16(uint32_t dst, const void* src) {
    asm volatile("cp.async.cg.shared.global [%0], [%1], 16;" :: "r"(dst), "l"(src));
}
__device__ __forceinline__ void cp_commit() { asm volatile("cp.async.commit_group;"); }
__device__ __forceinline__ void cp_wait0()  { asm volatile("cp.async.wait_group 0;"); }
__device__ __forceinline__ void cp_wait1()  { asm volatile("cp.async.wait_group 1;"); }

__global__ void rvq_prep_kernel(const float* __restrict__ cb) {
    int idx = blockIdx.x * blockDim.x + threadIdx.x;
    if (idx == 0) g_loss_acc = 0.0;
    const float* row = cb + (long)idx * Dd;
    float s = 0.f;
    #pragma unroll 8
    for (int d = 0; d < Dd; d++) s = fmaf(row[d], row[d], s);
    g_c2[idx] = s;
}

__global__ __launch_bounds__(NT, 1) void rvq_main_kernel(
    const float* __restrict__ z,  const float* __restrict__ cb,
    const float* __restrict__ Wi, const float* __restrict__ bi,
    const float* __restrict__ Wo, const float* __restrict__ bo,
    float* __restrict__ out, long out_elems, int fullout)
{
    extern __shared__ __align__(16) float sm[];
    float* residT = sm;                    // [1024][32]  (col-major residual)
    float* zeT    = sm + 32768;            // [256][32]
    float* wt     = sm + 40960;            // 16384 floats: staged tiles (+swapped copies)
    ull*   sbest  = (ull*)(sm + 57344);    // [32]
    float* spart  = sm + 57344 + 64;       // [8][32]
    float* srow   = spart + 256;           // [32]
    float* lred   = srow + 32;             // [8]

    const int tid  = threadIdx.x;
    const int warp = tid >> 5;
    const int lane = tid & 31;
    const int rA   = (warp & 3) * 8;       // 8 rows per warp group
    const int colg = warp >> 2;            // 0/1
    const int col0 = colg * 128 + lane * 4;
    const long row0 = (long)blockIdx.x * BR;

    const uint32_t wt_s = (uint32_t)__cvta_generic_to_shared(wt);

    const long SC_OFF   = (long)Bn * Cc;
    const long CODE_OFF = SC_OFF + 3;
    const long LAT_OFF  = CODE_OFF + (long)Bn * NCB;  // == 3 mod 4: scalar stores

    // ---- initial fill: residT = z^T ----
    {
        #pragma unroll
        for (int it = 0; it < 32; it++) {
            int f = tid + NT * it;          // float4 index over [32 r][256 c4]
            int r = f >> 8, c4 = f & 255;
            float4 v = ((const float4*)z)[(row0 + r) * 256 + c4];
            float* p = &residT[(c4 * 4) * 32 + r];
            p[0] = v.x; p[32] = v.y; p[64] = v.z; p[96] = v.w;
        }
    }
    __syncthreads();

    float loss_local = 0.f;

    for (int i = 0; i < NCB; i++) {
        const float* Wi_i = Wi + (long)i * Cc * Dd;
        const float* cb_i = cb + (long)i * Kk * Dd;
        const float* Wo_i = Wo + (long)i * Dd * Cc;
        const float* c2_i = g_c2 + i * Kk;

        // ============ Phase A: z_e = resid @ W_in + b_in ==================
        {
            ull accd[4][2], acca[4][2];
            #pragma unroll
            for (int rp = 0; rp < 4; rp++) {
                accd[rp][0] = accd[rp][1] = 0ull;
                acca[rp][0] = acca[rp][1] = 0ull;
            }
            __syncthreads();   // wt free from prior phase
            // stage tile 0 (normal region of buf 0)
            #pragma unroll
            for (int s = 0; s < 4; s++) {
                int f = tid + NT * s;
                cp16(wt_s + (uint32_t)f * 16, Wi_i + (long)f * 4);
            }
            cp_commit();

            for (int t = 0; t < 64; t++) {
                if (t < 63) {
                    uint32_t db = wt_s + (uint32_t)(((t + 1) & 1) * 8192) * 4;
                    const float* src = Wi_i + (long)(t + 1) * 4096;
                    #pragma unroll
                    for (int s = 0; s < 4; s++) {
                        int f = tid + NT * s;
                        cp16(db + (uint32_t)f * 16, src + (long)f * 4);
                    }
                    cp_commit();
                    cp_wait1();
                } else cp_wait0();
                float* wN = wt + (t & 1) * 8192;
                float* wS = wN + 4096;
                // build pair-swapped copy (reads own cp'd data only)
                #pragma unroll
                for (int s = 0; s < 4; s++) {
                    int f = tid + NT * s;
                    float4 v = *(const float4*)&wN[f * 4];
                    wS[f * 4 + 0] = v.y; wS[f * 4 + 1] = v.x;
                    wS[f * 4 + 2] = v.w; wS[f * 4 + 3] = v.z;
                }
                __syncthreads();
                #pragma unroll
                for (int kk = 0; kk < 16; kk++) {
                    const int kb = t * 16 + kk;
                    ulonglong2 a0 = *(const ulonglong2*)&residT[kb * 32 + rA];
                    ulonglong2 a1 = *(const ulonglong2*)&residT[kb * 32 + rA + 4];
                    ulonglong2 bn = *(const ulonglong2*)&wN[kk * 256 + col0];
                    ulonglong2 bs = *(const ulonglong2*)&wS[kk * 256 + col0];
                    ull ap[4] = {a0.x, a0.y, a1.x, a1.y};
                    #pragma unroll
                    for (int rp = 0; rp < 4; rp++) {
                        ffma2(accd[rp][0], ap[rp], bn.x);
                        ffma2(acca[rp][0], ap[rp], bs.x);
                        ffma2(accd[rp][1], ap[rp], bn.y);
                        ffma2(acca[rp][1], ap[rp], bs.y);
                    }
                }
                __syncthreads();
            }
            // epilogue: unscramble, bias, store zeT + latents
            float v[8][4];
            #pragma unroll
            for (int rp = 0; rp < 4; rp++)
                #pragma unroll
                for (int cp = 0; cp < 2; cp++) {
                    float lo, hi, lo2, hi2;
                    upk2(accd[rp][cp], lo, hi);
                    upk2(acca[rp][cp], lo2, hi2);
                    v[2 * rp][2 * cp]         = lo;
                    v[2 * rp + 1][2 * cp + 1] = hi;
                    v[2 * rp][2 * cp + 1]     = lo2;
                    v[2 * rp + 1][2 * cp]     = hi2;
                }
            float4 bia = *(const float4*)&bi[i * Dd + col0];
            const float bb[4] = {bia.x, bia.y, bia.z, bia.w};
            #pragma unroll
            for (int r = 0; r < 8; r++) {
                long o = LAT_OFF + (row0 + rA + r) * (long)(NCB * Dd) + (long)i * Dd + col0;
                #pragma unroll
                for (int j = 0; j < 4; j++) {
                    float val = v[r][j] + bb[j];
                    zeT[(col0 + j) * 32 + rA + r] = val;
                    if (fullout && o + j < out_elems) out[o + j] = val;
                }
            }
        }
        if (tid < BR) sbest[tid] = ~0ull;
        __syncthreads();

        // ---- per-row |z_e|^2 (thread: r=lane, d-range per warp) ----
        {
            float s = 0.f;
            #pragma unroll
            for (int d = 0; d < 32; d++) {
                float val = zeT[(warp * 32 + d) * 32 + lane];
                s = fmaf(val, val, s);
            }
            spart[warp * 32 + lane] = s;
        }
        __syncthreads();
        if (tid < 32) {
            float t = 0.f;
            #pragma unroll
            for (int g = 0; g < 8; g++) t += spart[g * 32 + tid];
            srow[tid] = t;
        }
        __syncthreads();

        // ============ Phase B: distances + argmin =========================
        for (int kc = 0; kc < Kk; kc += 256) {
            ull dotd[4][2], dota[4][2];
            #pragma unroll
            for (int rp = 0; rp < 4; rp++) {
                dotd[rp][0] = dotd[rp][1] = 0ull;
                dota[rp][0] = dota[rp][1] = 0ull;
            }
            float4 stg[4];
            #pragma unroll
            for (int s = 0; s < 4; s++) {
                int f = tid + NT * s, c = f >> 2, j = f & 3;
                stg[s] = *(const float4*)&cb_i[(long)(kc + c) * Dd + j * 4];
            }
            for (int dt = 0; dt < 16; dt++) {
                __syncthreads();
                #pragma unroll
                for (int s = 0; s < 4; s++) {
                    int f = tid + NT * s, c = f >> 2, j = f & 3;
                    int half = c >> 7, cl = c & 127;
                    float* pN = wt + half * 2112 + (4 * j) * CBT + cl;
                    float* pS = wt + 4224 + half * 2112 + (4 * j) * CBT + (cl ^ 1);
                    pN[0 * CBT] = stg[s].x; pN[1 * CBT] = stg[s].y;
                    pN[2 * CBT] = stg[s].z; pN[3 * CBT] = stg[s].w;
                    pS[0 * CBT] = stg[s].x; pS[1 * CBT] = stg[s].y;
                    pS[2 * CBT] = stg[s].z; pS[3 * CBT] = stg[s].w;
                }
                __syncthreads();
                if (dt < 15) {
                    #pragma unroll
                    for (int s = 0; s < 4; s++) {
                        int f = tid + NT * s, c = f >> 2, j = f & 3;
                        stg[s] = *(const float4*)&cb_i[(long)(kc + c) * Dd
                                                       + (dt + 1) * 16 + j * 4];
                    }
                }
                const float* wN = wt + colg * 2112;
                const float* wS = wt + 4224 + colg * 2112;
                #pragma unroll
                for (int dd = 0; dd < 16; dd++) {
                    const int d = dt * 16 + dd;
                    ulonglong2 a0 = *(const ulonglong2*)&zeT[d * 32 + rA];
                    ulonglong2 a1 = *(const ulonglong2*)&zeT[d * 32 + rA + 4];
                    ulonglong2 bn = *(const ulonglong2*)&wN[dd * CBT + lane * 4];
                    ulonglong2 bs = *(const ulonglong2*)&wS[dd * CBT + lane * 4];
                    ull ap[4] = {a0.x, a0.y, a1.x, a1.y};
                    #pragma unroll
                    for (int rp = 0; rp < 4; rp++) {
                        ffma2(dotd[rp][0], ap[rp], bn.x);
                        ffma2(dota[rp][0], ap[rp], bs.x);
                        ffma2(dotd[rp][1], ap[rp], bn.y);
                        ffma2(dota[rp][1], ap[rp], bs.y);
                    }
                }
            }
            // argmin epilogue (ref rounding: (s - 2*dot) + c2)
            float dv[8][4];
            #pragma unroll
            for (int rp = 0; rp < 4; rp++)
                #pragma unroll
                for (int cp = 0; cp < 2; cp++) {
                    float lo, hi, lo2, hi2;
                    upk2(dotd[rp][cp], lo, hi);
                    upk2(dota[rp][cp], lo2, hi2);
                    dv[2 * rp][2 * cp]         = lo;
                    dv[2 * rp + 1][2 * cp + 1] = hi;
                    dv[2 * rp][2 * cp + 1]     = lo2;
                    dv[2 * rp + 1][2 * cp]     = hi2;
                }
            const int code0 = kc + colg * 128 + lane * 4;
            float4 c2v = *(const float4*)&c2_i[code0];
            const float c2a[4] = {c2v.x, c2v.y, c2v.z, c2v.w};
            #pragma unroll
            for (int r = 0; r < 8; r++) {
                const float sr = srow[rA + r];
                float mval = __int_as_float(0x7f800000);
                int midx = 0;
                #pragma unroll
                for (int j = 0; j < 4; j++) {
                    float dvv = (sr - 2.0f * dv[r][j]) + c2a[j];
                    if (dvv < mval) { mval = dvv; midx = code0 + j; }
                }
                #pragma unroll
                for (int off = 16; off; off >>= 1) {
                    float ov = __shfl_down_sync(0xffffffffu, mval, off);
                    int   oi = __shfl_down_sync(0xffffffffu, midx, off);
                    if (ov < mval || (ov == mval && oi < midx)) { mval = ov; midx = oi; }
                }
                if (lane == 0) {
                    ull key = ((ull)__float_as_uint(mval) << 32) | (unsigned)midx;
                    atomicMin(&sbest[rA + r], key);
                }
            }
        }
        __syncthreads();

        // ====== Phase C: gather emb, commit loss, straight-through ========
        {
            int mycode = (int)(sbest[lane] & 0xffffffffu);
            float lp = 0.f;
            #pragma unroll
            for (int it = 0; it < 32; it++) {
                int d = warp * 32 + it;
                float zev = zeT[d * 32 + lane];
                float emb = __ldg(&cb_i[(long)mycode * Dd + d]);
                float diff = zev - emb;
                lp = fmaf(diff, diff, lp);
                zeT[d * 32 + lane] = zev + (emb - zev);
            }
            loss_local += lp;
        }
        if (fullout && tid < BR) {
            long o = CODE_OFF + (row0 + tid) * (long)NCB + i;
            if (o < out_elems) out[o] = (float)(int)(sbest[tid] & 0xffffffffu);
        }
        __syncthreads();

        // ============ Phase D: resid -= q @ W_out + b_out =================
        for (int nc = 0; nc < Cc; nc += 256) {
            ull accd[4][2], acca[4][2];
            #pragma unroll
            for (int rp = 0; rp < 4; rp++) {
                accd[rp][0] = accd[rp][1] = 0ull;
                acca[rp][0] = acca[rp][1] = 0ull;
            }
            __syncthreads();   // wt free
            #pragma unroll
            for (int s = 0; s < 4; s++) {
                int f = tid + NT * s, rr = f >> 6, cc = f & 63;
                cp16(wt_s + (uint32_t)f * 16, Wo_i + (long)rr * Cc + nc + cc * 4);
            }
            cp_commit();

            for (int t = 0; t < 16; t++) {
                if (t < 15) {
                    uint32_t db = wt_s + (uint32_t)(((t + 1) & 1) * 8192) * 4;
                    #pragma unroll
                    for (int s = 0; s < 4; s++) {
                        int f = tid + NT * s, rr = f >> 6, cc = f & 63;
                        cp16(db + (uint32_t)f * 16,
                             Wo_i + (long)((t + 1) * 16 + rr) * Cc + nc + cc * 4);
                    }
                    cp_commit();
                    cp_wait1();
                } else cp_wait0();
                float* wN = wt + (t & 1) * 8192;
                float* wS = wN + 4096;
                #pragma unroll
                for (int s = 0; s < 4; s++) {
                    int f = tid + NT * s;
                    float4 v = *(const float4*)&wN[f * 4];
                    wS[f * 4 + 0] = v.y; wS[f * 4 + 1] = v.x;
                    wS[f * 4 + 2] = v.w; wS[f * 4 + 3] = v.z;
                }
                __syncthreads();
                #pragma unroll
                for (int kk = 0; kk < 16; kk++) {
                    const int kb = t * 16 + kk;
                    ulonglong2 a0 = *(const ulonglong2*)&zeT[kb * 32 + rA];
                    ulonglong2 a1 = *(const ulonglong2*)&zeT[kb * 32 + rA + 4];
                    ulonglong2 bn = *(const ulonglong2*)&wN[kk * 256 + col0];
                    ulonglong2 bs = *(const ulonglong2*)&wS[kk * 256 + col0];
                    ull ap[4] = {a0.x, a0.y, a1.x, a1.y};
                    #pragma unroll
                    for (int rp = 0; rp < 4; rp++) {
                        ffma2(accd[rp][0], ap[rp], bn.x);
                        ffma2(acca[rp][0], ap[rp], bs.x);
                        ffma2(accd[rp][1], ap[rp], bn.y);
                        ffma2(acca[rp][1], ap[rp], bs.y);
                    }
                }
                __syncthreads();
            }
            // epilogue
            float v[8][4];
            #pragma unroll
            for (int rp = 0; rp < 4; rp++)
                #pragma unroll
                for (int cp = 0; cp < 2; cp++) {
                    float lo, hi, lo2, hi2;
                    upk2(accd[rp][cp], lo, hi);
                    upk2(acca[rp][cp], lo2, hi2);
                    v[2 * rp][2 * cp]         = lo;
                    v[2 * rp + 1][2 * cp + 1] = hi;
                    v[2 * rp][2 * cp + 1]     = lo2;
                    v[2 * rp + 1][2 * cp]     = hi2;
                }
            float4 bo4 = *(const float4*)&bo[i * Cc + nc + col0];
            const float bb[4] = {bo4.x, bo4.y, bo4.z, bo4.w};
            if (i < NCB - 1) {
                #pragma unroll
                for (int r = 0; r < 8; r++)
                    #pragma unroll
                    for (int j = 0; j < 4; j++)
                        residT[(nc + col0 + j) * 32 + rA + r] -= v[r][j] + bb[j];
            } else {
                // fused z_q output: z_q = z - (resid - qi)
                #pragma unroll
                for (int r = 0; r < 8; r++) {
                    const long grow = row0 + rA + r;
                    float4 zr = ((const float4*)z)[grow * 256 + (nc + col0) / 4];
                    const float za[4] = {zr.x, zr.y, zr.z, zr.w};
                    float o4[4];
                    #pragma unroll
                    for (int j = 0; j < 4; j++) {
                        float nr = residT[(nc + col0 + j) * 32 + rA + r] - (v[r][j] + bb[j]);
                        o4[j] = za[j] - nr;
                    }
                    ((float4*)out)[grow * 256 + (nc + col0) / 4] =
                        make_float4(o4[0], o4[1], o4[2], o4[3]);
                }
            }
        }
        __syncthreads();
    }

    // ---- loss reduction ----
    #pragma unroll
    for (int off = 16; off; off >>= 1)
        loss_local += __shfl_down_sync(0xffffffffu, loss_local, off);
    if (lane == 0) lred[warp] = loss_local;
    __syncthreads();
    if (warp == 0) {
        float v = (lane < 8) ? lred[lane] : 0.f;
        #pragma unroll
        for (int off = 4; off; off >>= 1)
            v += __shfl_down_sync(0xffffffffu, v, off);
        if (lane == 0) atomicAdd(&g_loss_acc, (double)v);
    }
}

__global__ void rvq_fin_kernel(float* __restrict__ out, long out_elems, int fullout) {
    if (fullout && threadIdx.x == 0) {
        long sc = (long)Bn * Cc;
        if (sc + 2 < out_elems) {
            double t = g_loss_acc;
            float enc = (float)(0.25 * t / ((double)Bn * (double)Dd));
            out[sc + 0] = enc;
            out[sc + 1] = enc;
            out[sc + 2] = 0.f;
        }
    }
}

extern "C" void kernel_launch(void* const* d_in, const int* in_sizes, int n_in,
                              void* d_out, int out_size) {
    const float* z  = (const float*)d_in[0];
    const float* cb = (const float*)d_in[1];
    const float* Wi = (const float*)d_in[2];
    const float* bi = (const float*)d_in[3];
    const float* Wo = (const float*)d_in[4];
    const float* bo = (const float*)d_in[5];
    float* out = (float*)d_out;

    const long out_elems = (long)out_size;
    const int fullout = out_elems > (long)Bn * Cc ? 1 : 0;

    const size_t smem = (size_t)57344 * sizeof(float)        // residT+zeT+wt
                      + 32 * sizeof(ull)                     // sbest
                      + (256 + 32 + 8) * sizeof(float);      // spart+srow+lred
    cudaFuncSetAttribute(rvq_main_kernel,
                         cudaFuncAttributeMaxDynamicSharedMemorySize, (int)smem);

    rvq_prep_kernel<<<(NCB * Kk) / 256, 256>>>(cb);
    rvq_main_kernel<<<Bn / BR, NT, smem>>>(z, cb, Wi, bi, Wo, bo, out, out_elems, fullout);
    rvq_fin_kernel<<<1, 32>>>(out, out_elems, fullout);
}

// round 8
// speedup vs baseline: 1.0007x; 1.0007x over previous
#include <cuda_runtime.h>
#include <cstdint>

// RVQ fused fp32 kernel, FFMA2 with zero-MOV operand feeding.
// Transposed activations in smem; diag/anti pair accumulation; swapped-copy tiles.
// B=65536, C=1024, D=256, K=2048, 4 codebooks. CTA = 32 rows, 256 threads, occ 1.

constexpr int Bn  = 65536;
constexpr int Cc  = 1024;
constexpr int Dd  = 256;
constexpr int Kk  = 2048;
constexpr int NCB = 4;
constexpr int BR  = 32;
constexpr int NT  = 256;
constexpr int CBT = 132;   // padded code stride for phase-B cbT tiles

typedef unsigned long long ull;

__device__ double g_loss_acc;
__device__ __align__(16) float g_c2[NCB * Kk];

__device__ __forceinline__ void upk2(ull v, float& lo, float& hi) {
    asm("mov.b64 {%0, %1}, %2;" : "=f"(lo), "=f"(hi) : "l"(v));
}
__device__ __forceinline__ void ffma2(ull& acc, ull a, ull b) {
    asm("fma.rn.f32x2 %0, %1, %2, %3;" : "=l"(acc) : "l"(a), "l"(b), "l"(acc));
}
__device__ __forceinline__ void cp16(uint32_t dst, const void* src) {
    asm volatile("cp.async.cg.shared.global [%0], [%1], 16;" :: "r"(dst), "l"(src));
}
__device__ __forceinline__ void cp_commit() { asm volatile("cp.async.commit_group;"); }
__device__ __forceinline__ void cp_wait0()  { asm volatile("cp.async.wait_group 0;"); }
__device__ __forceinline__ void cp_wait1()  { asm volatile("cp.async.wait_group 1;"); }

__global__ void rvq_prep_kernel(const float* __restrict__ cb) {
    int idx = blockIdx.x * blockDim.x + threadIdx.x;
    if (idx == 0) g_loss_acc = 0.0;
    const float* row = cb + (long)idx * Dd;
    float s = 0.f;
    #pragma unroll 8
    for (int d = 0; d < Dd; d++) s = fmaf(row[d], row[d], s);
    g_c2[idx] = s;
}

__global__ __launch_bounds__(NT, 1) void rvq_main_kernel(
    const float* __restrict__ z,  const float* __restrict__ cb,
    const float* __restrict__ Wi, const float* __restrict__ bi,
    const float* __restrict__ Wo, const float* __restrict__ bo,
    float* __restrict__ out, long out_elems, int fullout)
{
    extern __shared__ __align__(16) float sm[];
    float* residT = sm;                    // [1024][32]  (col-major residual)
    float* zeT    = sm + 32768;            // [256][32]
    float* wt     = sm + 40960;            // 16384 floats: staged tiles (+swapped copies)
    ull*   sbest  = (ull*)(sm + 57344);    // [32]
    float* spart  = sm + 57344 + 64;       // [8][32]
    float* srow   = spart + 256;           // [32]
    float* lred   = srow + 32;             // [8]

    const int tid  = threadIdx.x;
    const int warp = tid >> 5;
    const int lane = tid & 31;
    const int rA   = (warp & 3) * 8;       // 8 rows per warp group
    const int colg = warp >> 2;            // 0/1
    const int col0 = colg * 128 + lane * 4;
    const long row0 = (long)blockIdx.x * BR;

    const uint32_t wt_s = (uint32_t)__cvta_generic_to_shared(wt);

    const long SC_OFF   = (long)Bn * Cc;
    const long CODE_OFF = SC_OFF + 3;
    const long LAT_OFF  = CODE_OFF + (long)Bn * NCB;  // == 3 mod 4: scalar stores

    // ---- initial fill: residT = z^T ----
    {
        #pragma unroll
        for (int it = 0; it < 32; it++) {
            int f = tid + NT * it;          // float4 index over [32 r][256 c4]
            int r = f >> 8, c4 = f & 255;
            float4 v = ((const float4*)z)[(row0 + r) * 256 + c4];
            float* p = &residT[(c4 * 4) * 32 + r];
            p[0] = v.x; p[32] = v.y; p[64] = v.z; p[96] = v.w;
        }
    }
    __syncthreads();

    float loss_local = 0.f;

    for (int i = 0; i < NCB; i++) {
        const float* Wi_i = Wi + (long)i * Cc * Dd;
        const float* cb_i = cb + (long)i * Kk * Dd;
        const float* Wo_i = Wo + (long)i * Dd * Cc;
        const float* c2_i = g_c2 + i * Kk;

        // ============ Phase A: z_e = resid @ W_in + b_in ==================
        {
            ull accd[4][2], acca[4][2];
            #pragma unroll
            for (int rp = 0; rp < 4; rp++) {
                accd[rp][0] = accd[rp][1] = 0ull;
                acca[rp][0] = acca[rp][1] = 0ull;
            }
            __syncthreads();   // wt free from prior phase
            // stage tile 0 (normal region of buf 0)
            #pragma unroll
            for (int s = 0; s < 4; s++) {
                int f = tid + NT * s;
                cp16(wt_s + (uint32_t)f * 16, Wi_i + (long)f * 4);
            }
            cp_commit();

            for (int t = 0; t < 64; t++) {
                if (t < 63) {
                    uint32_t db = wt_s + (uint32_t)(((t + 1) & 1) * 8192) * 4;
                    const float* src = Wi_i + (long)(t + 1) * 4096;
                    #pragma unroll
                    for (int s = 0; s < 4; s++) {
                        int f = tid + NT * s;
                        cp16(db + (uint32_t)f * 16, src + (long)f * 4);
                    }
                    cp_commit();
                    cp_wait1();
                } else cp_wait0();
                float* wN = wt + (t & 1) * 8192;
                float* wS = wN + 4096;
                // build pair-swapped copy (reads own cp'd data only)
                #pragma unroll
                for (int s = 0; s < 4; s++) {
                    int f = tid + NT * s;
                    float4 v = *(const float4*)&wN[f * 4];
                    wS[f * 4 + 0] = v.y; wS[f * 4 + 1] = v.x;
                    wS[f * 4 + 2] = v.w; wS[f * 4 + 3] = v.z;
                }
                __syncthreads();
                #pragma unroll
                for (int kk = 0; kk < 16; kk++) {
                    const int kb = t * 16 + kk;
                    ulonglong2 a0 = *(const ulonglong2*)&residT[kb * 32 + rA];
                    ulonglong2 a1 = *(const ulonglong2*)&residT[kb * 32 + rA + 4];
                    ulonglong2 bn = *(const ulonglong2*)&wN[kk * 256 + col0];
                    ulonglong2 bs = *(const ulonglong2*)&wS[kk * 256 + col0];
                    ull ap[4] = {a0.x, a0.y, a1.x, a1.y};
                    #pragma unroll
                    for (int rp = 0; rp < 4; rp++) {
                        ffma2(accd[rp][0], ap[rp], bn.x);
                        ffma2(acca[rp][0], ap[rp], bs.x);
                        ffma2(accd[rp][1], ap[rp], bn.y);
                        ffma2(acca[rp][1], ap[rp], bs.y);
                    }
                }
                __syncthreads();
            }
            // epilogue: unscramble, bias, store zeT + latents
            float v[8][4];
            #pragma unroll
            for (int rp = 0; rp < 4; rp++)
                #pragma unroll
                for (int cp = 0; cp < 2; cp++) {
                    float lo, hi, lo2, hi2;
                    upk2(accd[rp][cp], lo, hi);
                    upk2(acca[rp][cp], lo2, hi2);
                    v[2 * rp][2 * cp]         = lo;
                    v[2 * rp + 1][2 * cp + 1] = hi;
                    v[2 * rp][2 * cp + 1]     = lo2;
                    v[2 * rp + 1][2 * cp]     = hi2;
                }
            float4 bia = *(const float4*)&bi[i * Dd + col0];
            const float bb[4] = {bia.x, bia.y, bia.z, bia.w};
            #pragma unroll
            for (int r = 0; r < 8; r++) {
                long o = LAT_OFF + (row0 + rA + r) * (long)(NCB * Dd) + (long)i * Dd + col0;
                #pragma unroll
                for (int j = 0; j < 4; j++) {
                    float val = v[r][j] + bb[j];
                    zeT[(col0 + j) * 32 + rA + r] = val;
                    if (fullout && o + j < out_elems) out[o + j] = val;
                }
            }
        }
        if (tid < BR) sbest[tid] = ~0ull;
        __syncthreads();

        // ---- per-row |z_e|^2 (thread: r=lane, d-range per warp) ----
        {
            float s = 0.f;
            #pragma unroll
            for (int d = 0; d < 32; d++) {
                float val = zeT[(warp * 32 + d) * 32 + lane];
                s = fmaf(val, val, s);
            }
            spart[warp * 32 + lane] = s;
        }
        __syncthreads();
        if (tid < 32) {
            float t = 0.f;
            #pragma unroll
            for (int g = 0; g < 8; g++) t += spart[g * 32 + tid];
            srow[tid] = t;
        }
        __syncthreads();

        // ============ Phase B: distances + argmin =========================
        for (int kc = 0; kc < Kk; kc += 256) {
            ull dotd[4][2], dota[4][2];
            #pragma unroll
            for (int rp = 0; rp < 4; rp++) {
                dotd[rp][0] = dotd[rp][1] = 0ull;
                dota[rp][0] = dota[rp][1] = 0ull;
            }
            float4 stg[4];
            #pragma unroll
            for (int s = 0; s < 4; s++) {
                int f = tid + NT * s, c = f >> 2, j = f & 3;
                stg[s] = *(const float4*)&cb_i[(long)(kc + c) * Dd + j * 4];
            }
            for (int dt = 0; dt < 16; dt++) {
                __syncthreads();
                #pragma unroll
                for (int s = 0; s < 4; s++) {
                    int f = tid + NT * s, c = f >> 2, j = f & 3;
                    int half = c >> 7, cl = c & 127;
                    float* pN = wt + half * 2112 + (4 * j) * CBT + cl;
                    float* pS = wt + 4224 + half * 2112 + (4 * j) * CBT + (cl ^ 1);
                    pN[0 * CBT] = stg[s].x; pN[1 * CBT] = stg[s].y;
                    pN[2 * CBT] = stg[s].z; pN[3 * CBT] = stg[s].w;
                    pS[0 * CBT] = stg[s].x; pS[1 * CBT] = stg[s].y;
                    pS[2 * CBT] = stg[s].z; pS[3 * CBT] = stg[s].w;
                }
                __syncthreads();
                if (dt < 15) {
                    #pragma unroll
                    for (int s = 0; s < 4; s++) {
                        int f = tid + NT * s, c = f >> 2, j = f & 3;
                        stg[s] = *(const float4*)&cb_i[(long)(kc + c) * Dd
                                                       + (dt + 1) * 16 + j * 4];
                    }
                }
                const float* wN = wt + colg * 2112;
                const float* wS = wt + 4224 + colg * 2112;
                #pragma unroll
                for (int dd = 0; dd < 16; dd++) {
                    const int d = dt * 16 + dd;
                    ulonglong2 a0 = *(const ulonglong2*)&zeT[d * 32 + rA];
                    ulonglong2 a1 = *(const ulonglong2*)&zeT[d * 32 + rA + 4];
                    ulonglong2 bn = *(const ulonglong2*)&wN[dd * CBT + lane * 4];
                    ulonglong2 bs = *(const ulonglong2*)&wS[dd * CBT + lane * 4];
                    ull ap[4] = {a0.x, a0.y, a1.x, a1.y};
                    #pragma unroll
                    for (int rp = 0; rp < 4; rp++) {
                        ffma2(dotd[rp][0], ap[rp], bn.x);
                        ffma2(dota[rp][0], ap[rp], bs.x);
                        ffma2(dotd[rp][1], ap[rp], bn.y);
                        ffma2(dota[rp][1], ap[rp], bs.y);
                    }
                }
            }
            // argmin epilogue (ref rounding: (s - 2*dot) + c2)
            float dv[8][4];
            #pragma unroll
            for (int rp = 0; rp < 4; rp++)
                #pragma unroll
                for (int cp = 0; cp < 2; cp++) {
                    float lo, hi, lo2, hi2;
                    upk2(dotd[rp][cp], lo, hi);
                    upk2(dota[rp][cp], lo2, hi2);
                    dv[2 * rp][2 * cp]         = lo;
                    dv[2 * rp + 1][2 * cp + 1] = hi;
                    dv[2 * rp][2 * cp + 1]     = lo2;
                    dv[2 * rp + 1][2 * cp]     = hi2;
                }
            const int code0 = kc + colg * 128 + lane * 4;
            float4 c2v = *(const float4*)&c2_i[code0];
            const float c2a[4] = {c2v.x, c2v.y, c2v.z, c2v.w};
            #pragma unroll
            for (int r = 0; r < 8; r++) {
                const float sr = srow[rA + r];
                float mval = __int_as_float(0x7f800000);
                int midx = 0;
                #pragma unroll
                for (int j = 0; j < 4; j++) {
                    float dvv = (sr - 2.0f * dv[r][j]) + c2a[j];
                    if (dvv < mval) { mval = dvv; midx = code0 + j; }
                }
                #pragma unroll
                for (int off = 16; off; off >>= 1) {
                    float ov = __shfl_down_sync(0xffffffffu, mval, off);
                    int   oi = __shfl_down_sync(0xffffffffu, midx, off);
                    if (ov < mval || (ov == mval && oi < midx)) { mval = ov; midx = oi; }
                }
                if (lane == 0) {
                    ull key = ((ull)__float_as_uint(mval) << 32) | (unsigned)midx;
                    atomicMin(&sbest[rA + r], key);
                }
            }
        }
        __syncthreads();

        // ====== Phase C: gather emb, commit loss, straight-through ========
        {
            int mycode = (int)(sbest[lane] & 0xffffffffu);
            float lp = 0.f;
            #pragma unroll
            for (int it = 0; it < 32; it++) {
                int d = warp * 32 + it;
                float zev = zeT[d * 32 + lane];
                float emb = __ldg(&cb_i[(long)mycode * Dd + d]);
                float diff = zev - emb;
                lp = fmaf(diff, diff, lp);
                zeT[d * 32 + lane] = zev + (emb - zev);
            }
            loss_local += lp;
        }
        if (fullout && tid < BR) {
            long o = CODE_OFF + (row0 + tid) * (long)NCB + i;
            if (o < out_elems) out[o] = (float)(int)(sbest[tid] & 0xffffffffu);
        }
        __syncthreads();

        // ============ Phase D: resid -= q @ W_out + b_out =================
        for (int nc = 0; nc < Cc; nc += 256) {
            ull accd[4][2], acca[4][2];
            #pragma unroll
            for (int rp = 0; rp < 4; rp++) {
                accd[rp][0] = accd[rp][1] = 0ull;
                acca[rp][0] = acca[rp][1] = 0ull;
            }
            __syncthreads();   // wt free
            #pragma unroll
            for (int s = 0; s < 4; s++) {
                int f = tid + NT * s, rr = f >> 6, cc = f & 63;
                cp16(wt_s + (uint32_t)f * 16, Wo_i + (long)rr * Cc + nc + cc * 4);
            }
            cp_commit();

            for (int t = 0; t < 16; t++) {
                if (t < 15) {
                    uint32_t db = wt_s + (uint32_t)(((t + 1) & 1) * 8192) * 4;
                    #pragma unroll
                    for (int s = 0; s < 4; s++) {
                        int f = tid + NT * s, rr = f >> 6, cc = f & 63;
                        cp16(db + (uint32_t)f * 16,
                             Wo_i + (long)((t + 1) * 16 + rr) * Cc + nc + cc * 4);
                    }
                    cp_commit();
                    cp_wait1();
                } else cp_wait0();
                float* wN = wt + (t & 1) * 8192;
                float* wS = wN + 4096;
                #pragma unroll
                for (int s = 0; s < 4; s++) {
                    int f = tid + NT * s;
                    float4 v = *(const float4*)&wN[f * 4];
                    wS[f * 4 + 0] = v.y; wS[f * 4 + 1] = v.x;
                    wS[f * 4 + 2] = v.w; wS[f * 4 + 3] = v.z;
                }
                __syncthreads();
                #pragma unroll
                for (int kk = 0; kk < 16; kk++) {
                    const int kb = t * 16 + kk;
                    ulonglong2 a0 = *(const ulonglong2*)&zeT[kb * 32 + rA];
                    ulonglong2 a1 = *(const ulonglong2*)&zeT[kb * 32 + rA + 4];
                    ulonglong2 bn = *(const ulonglong2*)&wN[kk * 256 + col0];
                    ulonglong2 bs = *(const ulonglong2*)&wS[kk * 256 + col0];
                    ull ap[4] = {a0.x, a0.y, a1.x, a1.y};
                    #pragma unroll
                    for (int rp = 0; rp < 4; rp++) {
                        ffma2(accd[rp][0], ap[rp], bn.x);
                        ffma2(acca[rp][0], ap[rp], bs.x);
                        ffma2(accd[rp][1], ap[rp], bn.y);
                        ffma2(acca[rp][1], ap[rp], bs.y);
                    }
                }
                __syncthreads();
            }
            // epilogue
            float v[8][4];
            #pragma unroll
            for (int rp = 0; rp < 4; rp++)
                #pragma unroll
                for (int cp = 0; cp < 2; cp++) {
                    float lo, hi, lo2, hi2;
                    upk2(accd[rp][cp], lo, hi);
                    upk2(acca[rp][cp], lo2, hi2);
                    v[2 * rp][2 * cp]         = lo;
                    v[2 * rp + 1][2 * cp + 1] = hi;
                    v[2 * rp][2 * cp + 1]     = lo2;
                    v[2 * rp + 1][2 * cp]     = hi2;
                }
            float4 bo4 = *(const float4*)&bo[i * Cc + nc + col0];
            const float bb[4] = {bo4.x, bo4.y, bo4.z, bo4.w};
            if (i < NCB - 1) {
                #pragma unroll
                for (int r = 0; r < 8; r++)
                    #pragma unroll
                    for (int j = 0; j < 4; j++)
                        residT[(nc + col0 + j) * 32 + rA + r] -= v[r][j] + bb[j];
            } else {
                // fused z_q output: z_q = z - (resid - qi)
                #pragma unroll
                for (int r = 0; r < 8; r++) {
                    const long grow = row0 + rA + r;
                    float4 zr = ((const float4*)z)[grow * 256 + (nc + col0) / 4];
                    const float za[4] = {zr.x, zr.y, zr.z, zr.w};
                    float o4[4];
                    #pragma unroll
                    for (int j = 0; j < 4; j++) {
                        float nr = residT[(nc + col0 + j) * 32 + rA + r] - (v[r][j] + bb[j]);
                        o4[j] = za[j] - nr;
                    }
                    ((float4*)out)[grow * 256 + (nc + col0) / 4] =
                        make_float4(o4[0], o4[1], o4[2], o4[3]);
                }
            }
        }
        __syncthreads();
    }

    // ---- loss reduction ----
    #pragma unroll
    for (int off = 16; off; off >>= 1)
        loss_local += __shfl_down_sync(0xffffffffu, loss_local, off);
    if (lane == 0) lred[warp] = loss_local;
    __syncthreads();
    if (warp == 0) {
        float v = (lane < 8) ? lred[lane] : 0.f;
        #pragma unroll
        for (int off = 4; off; off >>= 1)
            v += __shfl_down_sync(0xffffffffu, v, off);
        if (lane == 0) atomicAdd(&g_loss_acc, (double)v);
    }
}

__global__ void rvq_fin_kernel(float* __restrict__ out, long out_elems, int fullout) {
    if (fullout && threadIdx.x == 0) {
        long sc = (long)Bn * Cc;
        if (sc + 2 < out_elems) {
            double t = g_loss_acc;
            float enc = (float)(0.25 * t / ((double)Bn * (double)Dd));
            out[sc + 0] = enc;
            out[sc + 1] = enc;
            out[sc + 2] = 0.f;
        }
    }
}

extern "C" void kernel_launch(void* const* d_in, const int* in_sizes, int n_in,
                              void* d_out, int out_size) {
    const float* z  = (const float*)d_in[0];
    const float* cb = (const float*)d_in[1];
    const float* Wi = (const float*)d_in[2];
    const float* bi = (const float*)d_in[3];
    const float* Wo = (const float*)d_in[4];
    const float* bo = (const float*)d_in[5];
    float* out = (float*)d_out;

    const long out_elems = (long)out_size;
    const int fullout = out_elems > (long)Bn * Cc ? 1 : 0;

    const size_t smem = (size_t)57344 * sizeof(float)        // residT+zeT+wt
                      + 32 * sizeof(ull)                     // sbest
                      + (256 + 32 + 8) * sizeof(float);      // spart+srow+lred
    cudaFuncSetAttribute(rvq_main_kernel,
                         cudaFuncAttributeMaxDynamicSharedMemorySize, (int)smem);

    rvq_prep_kernel<<<(NCB * Kk) / 256, 256>>>(cb);
    rvq_main_kernel<<<Bn / BR, NT, smem>>>(z, cb, Wi, bi, Wo, bo, out, out_elems, fullout);
    rvq_fin_kernel<<<1, 32>>>(out, out_elems, fullout);
}

// round 14
// speedup vs baseline: 1.3713x; 1.3703x over previous
#include <cuda_runtime.h>
#include <cuda_fp16.h>
#include <cstdint>

typedef unsigned long long ull;
constexpr int Bn=65536, Cc=1024, Dd=256, Kk=2048, NCB=4;
constexpr long SC_OFF=(long)Bn*Cc, CODE_OFF=SC_OFF+3, LAT_OFF=CODE_OFF+(long)Bn*NCB;
constexpr float SPL = 2048.f, SPLI = 1.f/2048.f;
constexpr float MARGIN = 1e-3f;

// smem (bytes): 3 x A[128x72h], 3 x B[64x72h]
constexpr uint32_t AHs=0, AMs=18432, ALs=36864;
constexpr uint32_t BHs=55296, BMs=64512, BLs=73728, SMEMB=82944;

// ---- static scratch ----
__device__ float g_resid[(size_t)Bn*Cc];
__device__ float g_ze[(size_t)Bn*Dd];
__device__ float g_zsq[Bn];
__device__ int   g_idx[Bn];
__device__ ull   g_cand[(size_t)Bn*128];   // per row: 32 blocks x 2 halves x top-2
__device__ float g_c2[NCB*Kk];
__device__ double g_loss;
__device__ __align__(128) __half g_WiH[(size_t)NCB*Dd*Cc]; // [i][n=256][k=1024]
__device__ __align__(128) __half g_WiM[(size_t)NCB*Dd*Cc];
__device__ __align__(128) __half g_WiL[(size_t)NCB*Dd*Cc];
__device__ __align__(128) __half g_cbH[(size_t)NCB*Kk*Dd]; // [i][n=2048][k=256]
__device__ __align__(128) __half g_cbM[(size_t)NCB*Kk*Dd];
__device__ __align__(128) __half g_cbL[(size_t)NCB*Kk*Dd];
__device__ __align__(128) __half g_WoH[(size_t)NCB*Cc*Dd]; // [i][n=1024][k=256]
__device__ __align__(128) __half g_WoM[(size_t)NCB*Cc*Dd];
__device__ __align__(128) __half g_WoL[(size_t)NCB*Cc*Dd];

// ---- helpers ----
__device__ __forceinline__ uint32_t smem_u32(const void* p){
    uint32_t a; asm("{ .reg .u64 t; cvta.to.shared.u64 t, %1; cvt.u32.u64 %0, t; }":"=r"(a):"l"(p)); return a;
}
__device__ __forceinline__ void cp16(uint32_t d, const void* s){
    asm volatile("cp.async.cg.shared.global [%0], [%1], 16;"::"r"(d),"l"(s));
}
__device__ __forceinline__ void ldsm4(uint32_t* r, uint32_t a){
    asm volatile("ldmatrix.sync.aligned.m8n8.x4.shared.b16 {%0,%1,%2,%3}, [%4];"
                 :"=r"(r[0]),"=r"(r[1]),"=r"(r[2]),"=r"(r[3]):"r"(a));
}
__device__ __forceinline__ void ldsm2(uint32_t& r0,uint32_t& r1, uint32_t a){
    asm volatile("ldmatrix.sync.aligned.m8n8.x2.shared.b16 {%0,%1}, [%2];"
                 :"=r"(r0),"=r"(r1):"r"(a));
}
__device__ __forceinline__ void mma16816(float* c, const uint32_t* a, uint32_t b0, uint32_t b1){
    asm volatile("mma.sync.aligned.m16n8k16.row.col.f32.f16.f16.f32 "
                 "{%0,%1,%2,%3},{%4,%5,%6,%7},{%8,%9},{%0,%1,%2,%3};"
                 :"+f"(c[0]),"+f"(c[1]),"+f"(c[2]),"+f"(c[3])
                 :"r"(a[0]),"r"(a[1]),"r"(a[2]),"r"(a[3]),"r"(b0),"r"(b1));
}
// zero-C variant: d = A@B + 0 (fresh accumulator, no carried bias)
__device__ __forceinline__ void mma16816_z(float* d, const uint32_t* a, uint32_t b0, uint32_t b1){
    asm volatile("mma.sync.aligned.m16n8k16.row.col.f32.f16.f16.f32 "
                 "{%0,%1,%2,%3},{%4,%5,%6,%7},{%8,%9},{%10,%11,%12,%13};"
                 :"=f"(d[0]),"=f"(d[1]),"=f"(d[2]),"=f"(d[3])
                 :"r"(a[0]),"r"(a[1]),"r"(a[2]),"r"(a[3]),"r"(b0),"r"(b1),
                  "f"(0.f),"f"(0.f),"f"(0.f),"f"(0.f));
}
__device__ __forceinline__ void split3(float x, __half& h, __half& m, __half& l){
    h = __float2half_rn(x);
    float r1 = x - __half2float(h);
    m = __float2half_rn(r1 * SPL);
    float r2 = r1 - __half2float(m) * SPLI;
    l = __float2half_rn(r2 * (SPL * SPL));
}

struct Acc { float hh[2][4][4]; float x1[2][4][4]; float x2[2][4][4]; };
__device__ __forceinline__ float comb(const Acc& a, int mt,int nt,int ci){
    return fmaf(SPLI, fmaf(SPLI, a.x2[mt][nt][ci], a.x1[mt][nt][ci]), a.hh[mt][nt][ci]);
}

// ---- mainloop: acc += split3(A[128 x 64*KCH]) @ split3(B[64 x 64*KCH])^T ----
// EXACT: hh accumulated via zero-init mma + RN FADD (kills carried-acc truncation bias)
template<int KCH, bool EXACT>
__device__ __forceinline__ void gemm_run(
    const float* __restrict__ Agl, int astride,
    const __half* __restrict__ Bh, const __half* __restrict__ Bm,
    const __half* __restrict__ Bl, int bK,
    char* sm, uint32_t sb, int tid, int lane, int warpR0, int warpC0, Acc& ac)
{
    #pragma unroll
    for (int mt=0;mt<2;mt++)
        #pragma unroll
        for (int nt=0;nt<4;nt++)
            #pragma unroll
            for (int ci=0;ci<4;ci++){ ac.hh[mt][nt][ci]=0.f; ac.x1[mt][nt][ci]=0.f; ac.x2[mt][nt][ci]=0.f; }

    const uint32_t aro = (uint32_t)((warpR0 + (lane&15))*144 + (lane>>4)*16);
    const uint32_t bro = (uint32_t)((warpC0 + (lane&7))*144 + ((lane>>3)&1)*16);

    for (int c=0;c<KCH;c++){
        const int kc = c*64;
        #pragma unroll
        for (int s=0;s<8;s++){
            int f = tid + 256*s, r = f>>4, j = f&15;
            float4 v = *(const float4*)(Agl + (size_t)r*astride + kc + j*4);
            __half h0,h1,h2,h3,m0,m1,m2,m3,l0,l1,l2,l3;
            split3(v.x,h0,m0,l0); split3(v.y,h1,m1,l1);
            split3(v.z,h2,m2,l2); split3(v.w,h3,m3,l3);
            uint32_t off = (uint32_t)(r*144 + j*8);
            *(__half2*)(sm + AHs + off)     = __halves2half2(h0,h1);
            *(__half2*)(sm + AHs + off + 4) = __halves2half2(h2,h3);
            *(__half2*)(sm + AMs + off)     = __halves2half2(m0,m1);
            *(__half2*)(sm + AMs + off + 4) = __halves2half2(m2,m3);
            *(__half2*)(sm + ALs + off)     = __halves2half2(l0,l1);
            *(__half2*)(sm + ALs + off + 4) = __halves2half2(l2,l3);
        }
        #pragma unroll
        for (int s=0;s<2;s++){
            int f = tid + 256*s, r = f>>3, u = f&7;
            cp16(sb + BHs + r*144 + u*16, Bh + (size_t)r*bK + kc + u*8);
            cp16(sb + BMs + r*144 + u*16, Bm + (size_t)r*bK + kc + u*8);
            cp16(sb + BLs + r*144 + u*16, Bl + (size_t)r*bK + kc + u*8);
        }
        asm volatile("cp.async.commit_group;");
        asm volatile("cp.async.wait_group 0;");
        __syncthreads();
        #pragma unroll
        for (int kt=0;kt<4;kt++){
            uint32_t ah[2][4], am[2][4], al[2][4];
            #pragma unroll
            for (int mt=0;mt<2;mt++){
                ldsm4(ah[mt], sb + AHs + aro + mt*2304 + kt*32);
                ldsm4(am[mt], sb + AMs + aro + mt*2304 + kt*32);
                ldsm4(al[mt], sb + ALs + aro + mt*2304 + kt*32);
            }
            #pragma unroll
            for (int nt=0;nt<4;nt++){
                uint32_t bh0,bh1,bm0,bm1,bl0,bl1;
                ldsm2(bh0,bh1, sb + BHs + bro + nt*1152 + kt*32);
                ldsm2(bm0,bm1, sb + BMs + bro + nt*1152 + kt*32);
                ldsm2(bl0,bl1, sb + BLs + bro + nt*1152 + kt*32);
                #pragma unroll
                for (int mt=0;mt<2;mt++){
                    if (EXACT){
                        float t[4];
                        mma16816_z(t, ah[mt], bh0, bh1);
                        #pragma unroll
                        for (int ci=0;ci<4;ci++) ac.hh[mt][nt][ci] += t[ci];
                    } else {
                        mma16816(ac.hh[mt][nt], ah[mt], bh0, bh1);
                    }
                    mma16816(ac.x1[mt][nt], ah[mt], bm0, bm1);
                    mma16816(ac.x1[mt][nt], am[mt], bh0, bh1);
                    mma16816(ac.x2[mt][nt], am[mt], bm0, bm1);
                    mma16816(ac.x2[mt][nt], ah[mt], bl0, bl1);
                    mma16816(ac.x2[mt][nt], al[mt], bh0, bh1);
                }
            }
        }
        __syncthreads();
    }
}

// ---- prep ----
__global__ void k_prep_misc(const float* __restrict__ cb){
    int idx = blockIdx.x*blockDim.x + threadIdx.x;
    if (idx==0) g_loss = 0.0;
    const float* row = cb + (long)idx*Dd; float s=0.f;
    #pragma unroll 8
    for (int d=0; d<Dd; d++) s = fmaf(row[d], row[d], s);
    g_c2[idx] = s;
}
__global__ void k_prep_wi(const float* __restrict__ Wi){
    int idx = blockIdx.x*256 + threadIdx.x;
    int n = idx & 255, k = (idx>>8) & 1023, i = idx>>18;
    __half h,m,l; split3(Wi[idx], h, m, l);
    size_t o = ((size_t)i*Dd + n)*Cc + k;
    g_WiH[o]=h; g_WiM[o]=m; g_WiL[o]=l;
}
__global__ void k_prep_cb(const float* __restrict__ cb){
    int idx = blockIdx.x*256 + threadIdx.x;
    __half h,m,l; split3(cb[idx], h, m, l);
    g_cbH[idx]=h; g_cbM[idx]=m; g_cbL[idx]=l;
}
__global__ void k_prep_wo(const float* __restrict__ Wo){
    int idx = blockIdx.x*256 + threadIdx.x;
    int n = idx & 1023, k = (idx>>10) & 255, i = idx>>18;
    __half h,m,l; split3(Wo[idx], h, m, l);
    size_t o = ((size_t)i*Cc + n)*Dd + k;
    g_WoH[o]=h; g_WoM[o]=m; g_WoL[o]=l;
}

// ---- GEMM1: z_e = resid @ Wi + bi ----
__global__ __launch_bounds__(256,1) void k_gemm1(const float* __restrict__ z,
        const float* __restrict__ bi_i, float* __restrict__ out, int fo, int icb){
    extern __shared__ __align__(16) char sm[];
    uint32_t sb = smem_u32(sm);
    int tid=threadIdx.x, lane=tid&31, warp=tid>>5;
    int warpR0=(warp&3)*32, warpC0=(warp>>2)*32;
    long m0 = (long)blockIdx.x*128; int n0 = blockIdx.y*64;
    const float* Agl = (icb ? g_resid : z) + m0*Cc;
    size_t bo_ = ((size_t)icb*Dd + n0)*Cc;
    Acc ac;
    gemm_run<16,true>(Agl, Cc, g_WiH+bo_, g_WiM+bo_, g_WiL+bo_, Cc, sm, sb, tid, lane, warpR0, warpC0, ac);
    int tr = lane>>2, tc = (lane&3)*2;
    #pragma unroll
    for (int mt=0;mt<2;mt++)
    #pragma unroll
    for (int hv=0;hv<2;hv++){
        long gr = m0 + warpR0 + mt*16 + tr + 8*hv;
        #pragma unroll
        for (int nt=0;nt<4;nt++){
            int cg = n0 + warpC0 + nt*8 + tc;
            float v0 = comb(ac,mt,nt,hv*2+0) + bi_i[cg];
            float v1 = comb(ac,mt,nt,hv*2+1) + bi_i[cg+1];
            *(float2*)(g_ze + gr*Dd + cg) = make_float2(v0, v1);
            if (fo){
                long o = LAT_OFF + gr*(long)(NCB*Dd) + (long)icb*Dd + cg;
                out[o] = v0; out[o+1] = v1;
            }
        }
    }
}

// ---- zsq ----
__global__ void k_zsq(){
    int warp = threadIdx.x>>5, lane = threadIdx.x&31;
    long row = (long)blockIdx.x*8 + warp;
    const float* p = g_ze + row*Dd;
    float s = 0.f;
    #pragma unroll
    for (int j=0;j<8;j++){ float v = p[lane + 32*j]; s = fmaf(v,v,s); }
    #pragma unroll
    for (int off=16; off; off>>=1) s += __shfl_down_sync(0xffffffffu, s, off);
    if (lane==0) g_zsq[row] = s;
}

// ---- DIST: TC distances -> top-2 candidates per (row, 32-code half) ----
__global__ __launch_bounds__(256,1) void k_dist(int icb){
    extern __shared__ __align__(16) char sm[];
    uint32_t sb = smem_u32(sm);
    int tid=threadIdx.x, lane=tid&31, warp=tid>>5;
    int colg = warp>>2;
    int warpR0=(warp&3)*32, warpC0=colg*32;
    long m0 = (long)blockIdx.x*128; int n0 = blockIdx.y*64;
    size_t bo_ = ((size_t)icb*Kk + n0)*Dd;
    Acc ac;
    gemm_run<4,false>(g_ze + m0*Dd, Dd, g_cbH+bo_, g_cbM+bo_, g_cbL+bo_, Dd, sm, sb, tid, lane, warpR0, warpC0, ac);
    const float* c2p = g_c2 + icb*Kk;
    int tr = lane>>2, tc = (lane&3)*2;
    const int slot0 = (blockIdx.y*2 + colg)*2;   // per (block, col-half) slots
    #pragma unroll
    for (int mt=0;mt<2;mt++)
    #pragma unroll
    for (int hv=0;hv<2;hv++){
        long gr = m0 + warpR0 + mt*16 + tr + 8*hv;
        float zs = g_zsq[gr];
        float dvv[8]; int cgg[8];
        #pragma unroll
        for (int nt=0;nt<4;nt++)
            #pragma unroll
            for (int jj=0;jj<2;jj++){
                int q = nt*2+jj;
                cgg[q] = n0 + warpC0 + nt*8 + tc + jj;
                dvv[q] = (zs - 2.0f*comb(ac,mt,nt,hv*2+jj)) + c2p[cgg[q]];
            }
        float m1v = dvv[0]; int m1i = cgg[0];
        #pragma unroll
        for (int q=1;q<8;q++) if (dvv[q] < m1v || (dvv[q]==m1v && cgg[q]<m1i)){ m1v=dvv[q]; m1i=cgg[q]; }
        #pragma unroll
        for (int off=1; off<4; off<<=1){
            float ov = __shfl_xor_sync(0xffffffffu, m1v, off);
            int   oi = __shfl_xor_sync(0xffffffffu, m1i, off);
            if (ov < m1v || (ov == m1v && oi < m1i)){ m1v=ov; m1i=oi; }
        }
        float m2v = __int_as_float(0x7f800000); int m2i = 0x7fffffff;
        #pragma unroll
        for (int q=0;q<8;q++)
            if (cgg[q]!=m1i && (dvv[q] < m2v || (dvv[q]==m2v && cgg[q]<m2i))){ m2v=dvv[q]; m2i=cgg[q]; }
        #pragma unroll
        for (int off=1; off<4; off<<=1){
            float ov = __shfl_xor_sync(0xffffffffu, m2v, off);
            int   oi = __shfl_xor_sync(0xffffffffu, m2i, off);
            if (ov < m2v || (ov == m2v && oi < m2i)){ m2v=ov; m2i=oi; }
        }
        if ((lane&3)==0){
            g_cand[gr*128 + slot0 + 0] = ((ull)__float_as_uint(m1v)<<32) | (unsigned)m1i;
            g_cand[gr*128 + slot0 + 1] = ((ull)__float_as_uint(m2v)<<32) | (unsigned)m2i;
        }
    }
}

// ---- PICK: exact fp32 rescore of margin candidates; warp per row ----
__global__ __launch_bounds__(256) void k_pick(const float* __restrict__ cb, int icb){
    int warp = threadIdx.x>>5, lane = threadIdx.x&31;
    long row = (long)blockIdx.x*8 + warp;
    ull cc[4];
    #pragma unroll
    for (int s=0;s<4;s++) cc[s] = g_cand[row*128 + lane*4 + s];
    float mv = __int_as_float(0x7f800000);
    #pragma unroll
    for (int s=0;s<4;s++) mv = fminf(mv, __uint_as_float((uint32_t)(cc[s]>>32)));
    #pragma unroll
    for (int off=16; off; off>>=1) mv = fminf(mv, __shfl_xor_sync(0xffffffffu, mv, off));
    float thr = mv + MARGIN;
    const float* zep = g_ze + row*Dd;
    float zs = g_zsq[row];
    const float* c2p = g_c2 + icb*Kk;
    float bde = __int_as_float(0x7f800000); int bcg = 0x7fffffff;
    #pragma unroll
    for (int s=0;s<4;s++){
        float dv = __uint_as_float((uint32_t)(cc[s]>>32));
        int cg = (int)(cc[s] & 0xffffffffu);
        if (dv <= thr){
            const float* cbp = cb + ((long)icb*Kk + cg)*Dd;
            float dot = 0.f;
            #pragma unroll 8
            for (int j=0;j<64;j++){
                float4 a = *(const float4*)(zep + 4*j);
                float4 b = __ldg((const float4*)(cbp + 4*j));
                dot = fmaf(a.x,b.x,dot); dot = fmaf(a.y,b.y,dot);
                dot = fmaf(a.z,b.z,dot); dot = fmaf(a.w,b.w,dot);
            }
            float de = (zs - 2.0f*dot) + c2p[cg];
            if (de < bde || (de == bde && cg < bcg)){ bde = de; bcg = cg; }
        }
    }
    #pragma unroll
    for (int off=16; off; off>>=1){
        float od = __shfl_xor_sync(0xffffffffu, bde, off);
        int   oc = __shfl_xor_sync(0xffffffffu, bcg, off);
        if (od < bde || (od == bde && oc < bcg)){ bde = od; bcg = oc; }
    }
    if (lane==0) g_idx[row] = bcg;
}

// ---- GATHER: q, commit loss, codes ----
__global__ __launch_bounds__(256) void k_gather(const float* __restrict__ cb,
        float* __restrict__ out, int fo, int icb){
    int tid = threadIdx.x, lane = tid&31, warp = tid>>5;
    long gid = (long)blockIdx.x*256 + tid;
    long row = gid >> 2; int seg = (int)(gid & 3) * 64;
    int code = g_idx[row];
    const float* ep = cb + ((long)icb*Kk + code)*Dd + seg;
    float* zp = g_ze + row*Dd + seg;
    float lp = 0.f;
    #pragma unroll
    for (int j=0;j<16;j++){
        float4 ze4 = *(const float4*)(zp + 4*j);
        float4 e4  = *(const float4*)(ep + 4*j);
        float d0 = ze4.x-e4.x, d1 = ze4.y-e4.y, d2 = ze4.z-e4.z, d3 = ze4.w-e4.w;
        lp = fmaf(d0,d0,fmaf(d1,d1,fmaf(d2,d2,fmaf(d3,d3,lp))));
        *(float4*)(zp + 4*j) = make_float4(ze4.x+(e4.x-ze4.x), ze4.y+(e4.y-ze4.y),
                                           ze4.z+(e4.z-ze4.z), ze4.w+(e4.w-ze4.w));
    }
    if (fo && (gid&3)==0) out[CODE_OFF + row*NCB + icb] = (float)code;
    #pragma unroll
    for (int off=16; off; off>>=1) lp += __shfl_down_sync(0xffffffffu, lp, off);
    __shared__ float wr[8];
    if (lane==0) wr[warp] = lp;
    __syncthreads();
    if (tid==0){ float s=0.f; for (int w=0;w<8;w++) s += wr[w]; atomicAdd(&g_loss, (double)s); }
}

// ---- GEMM3: resid -= q @ Wo + bo ; last: z_q = z - resid ----
__global__ __launch_bounds__(256,1) void k_gemm3(const float* __restrict__ z,
        const float* __restrict__ bo_i, float* __restrict__ out, int icb){
    extern __shared__ __align__(16) char sm[];
    uint32_t sb = smem_u32(sm);
    int tid=threadIdx.x, lane=tid&31, warp=tid>>5;
    int warpR0=(warp&3)*32, warpC0=(warp>>2)*32;
    long m0 = (long)blockIdx.x*128; int n0 = blockIdx.y*64;
    size_t bo_ = ((size_t)icb*Cc + n0)*Dd;
    Acc ac;
    gemm_run<4,true>(g_ze + m0*Dd, Dd, g_WoH+bo_, g_WoM+bo_, g_WoL+bo_, Dd, sm, sb, tid, lane, warpR0, warpC0, ac);
    const float* rsrc = (icb ? g_resid : z);
    const int last = (icb == NCB-1);
    int tr = lane>>2, tc = (lane&3)*2;
    #pragma unroll
    for (int mt=0;mt<2;mt++)
    #pragma unroll
    for (int hv=0;hv<2;hv++){
        long gr = m0 + warpR0 + mt*16 + tr + 8*hv;
        #pragma unroll
        for (int nt=0;nt<4;nt++){
            int cg = n0 + warpC0 + nt*8 + tc;
            float v0 = comb(ac,mt,nt,hv*2+0) + bo_i[cg];
            float v1 = comb(ac,mt,nt,hv*2+1) + bo_i[cg+1];
            float2 rv = *(const float2*)(rsrc + gr*Cc + cg);
            float nr0 = rv.x - v0, nr1 = rv.y - v1;
            *(float2*)(g_resid + gr*Cc + cg) = make_float2(nr0, nr1);
            if (last){
                float2 zz = *(const float2*)(z + gr*Cc + cg);
                *(float2*)(out + gr*Cc + cg) = make_float2(zz.x - nr0, zz.y - nr1);
            }
        }
    }
}

__global__ void k_fin(float* __restrict__ out, int fo){
    if (fo && threadIdx.x==0){
        double t = g_loss;
        float enc = (float)(0.25 * t / ((double)Bn * (double)Dd));
        out[SC_OFF+0] = enc; out[SC_OFF+1] = enc; out[SC_OFF+2] = 0.f;
    }
}

extern "C" void kernel_launch(void* const* d_in, const int* in_sizes, int n_in,
                              void* d_out, int out_size) {
    const float* z  = (const float*)d_in[0];
    const float* cb = (const float*)d_in[1];
    const float* Wi = (const float*)d_in[2];
    const float* bi = (const float*)d_in[3];
    const float* Wo = (const float*)d_in[4];
    const float* bo = (const float*)d_in[5];
    float* out = (float*)d_out;
    const int fo = ((long)out_size > SC_OFF) ? 1 : 0;

    cudaFuncSetAttribute(k_gemm1, cudaFuncAttributeMaxDynamicSharedMemorySize, SMEMB);
    cudaFuncSetAttribute(k_dist,  cudaFuncAttributeMaxDynamicSharedMemorySize, SMEMB);
    cudaFuncSetAttribute(k_gemm3, cudaFuncAttributeMaxDynamicSharedMemorySize, SMEMB);

    k_prep_misc<<<NCB*Kk/256, 256>>>(cb);
    k_prep_wi<<<(NCB*Cc*Dd)/256, 256>>>(Wi);
    k_prep_cb<<<(NCB*Kk*Dd)/256, 256>>>(cb);
    k_prep_wo<<<(NCB*Dd*Cc)/256, 256>>>(Wo);

    for (int i=0;i<NCB;i++){
        k_gemm1<<<dim3(512,4), 256, SMEMB>>>(z, bi + i*Dd, out, fo, i);
        k_zsq<<<Bn/8, 256>>>();
        k_dist<<<dim3(512,32), 256, SMEMB>>>(i);
        k_pick<<<Bn/8, 256>>>(cb, i);
        k_gather<<<Bn*4/256, 256>>>(cb, out, fo, i);
        k_gemm3<<<dim3(512,16), 256, SMEMB>>>(z, bo + i*Cc, out, i);
    }
    k_fin<<<1, 32>>>(out, fo);
}

// round 15
// speedup vs baseline: 1.7932x; 1.3077x over previous
#include <cuda_runtime.h>
#include <cuda_fp16.h>
#include <cstdint>

typedef unsigned long long ull;
constexpr int Bn=65536, Cc=1024, Dd=256, Kk=2048, NCB=4;
constexpr long SC_OFF=(long)Bn*Cc, CODE_OFF=SC_OFF+3, LAT_OFF=CODE_OFF+(long)Bn*NCB;
constexpr float SPL = 2048.f, SPLI = 1.f/2048.f;
constexpr float MARGIN = 1e-3f;

// per-buffer smem offsets (bytes); two buffers for double-buffering
constexpr uint32_t AHs=0, AMs=18432, ALs=36864;
constexpr uint32_t BHs=55296, BMs=64512, BLs=73728;
constexpr uint32_t BUFB=82944, SMEMB=2*BUFB;   // 165888

// ---- static scratch ----
__device__ float g_resid[(size_t)Bn*Cc];
__device__ float g_ze[(size_t)Bn*Dd];
__device__ float g_zsq[Bn];
__device__ int   g_idx[Bn];
__device__ ull   g_cand[(size_t)Bn*128];
__device__ float g_c2[NCB*Kk];
__device__ double g_loss;
// pre-split activations (written by prep / gemm epilogues)
__device__ __align__(128) __half g_rH[(size_t)Bn*Cc];
__device__ __align__(128) __half g_rM[(size_t)Bn*Cc];
__device__ __align__(128) __half g_rL[(size_t)Bn*Cc];
__device__ __align__(128) __half g_zeH[(size_t)Bn*Dd];
__device__ __align__(128) __half g_zeM[(size_t)Bn*Dd];
__device__ __align__(128) __half g_zeL[(size_t)Bn*Dd];
// pre-split weights
__device__ __align__(128) __half g_WiH[(size_t)NCB*Dd*Cc];
__device__ __align__(128) __half g_WiM[(size_t)NCB*Dd*Cc];
__device__ __align__(128) __half g_WiL[(size_t)NCB*Dd*Cc];
__device__ __align__(128) __half g_cbH[(size_t)NCB*Kk*Dd];
__device__ __align__(128) __half g_cbM[(size_t)NCB*Kk*Dd];
__device__ __align__(128) __half g_cbL[(size_t)NCB*Kk*Dd];
__device__ __align__(128) __half g_WoH[(size_t)NCB*Cc*Dd];
__device__ __align__(128) __half g_WoM[(size_t)NCB*Cc*Dd];
__device__ __align__(128) __half g_WoL[(size_t)NCB*Cc*Dd];

// ---- helpers ----
__device__ __forceinline__ uint32_t smem_u32(const void* p){
    uint32_t a; asm("{ .reg .u64 t; cvta.to.shared.u64 t, %1; cvt.u32.u64 %0, t; }":"=r"(a):"l"(p)); return a;
}
__device__ __forceinline__ void cp16(uint32_t d, const void* s){
    asm volatile("cp.async.cg.shared.global [%0], [%1], 16;"::"r"(d),"l"(s));
}
__device__ __forceinline__ void ldsm4(uint32_t* r, uint32_t a){
    asm volatile("ldmatrix.sync.aligned.m8n8.x4.shared.b16 {%0,%1,%2,%3}, [%4];"
                 :"=r"(r[0]),"=r"(r[1]),"=r"(r[2]),"=r"(r[3]):"r"(a));
}
__device__ __forceinline__ void ldsm2(uint32_t& r0,uint32_t& r1, uint32_t a){
    asm volatile("ldmatrix.sync.aligned.m8n8.x2.shared.b16 {%0,%1}, [%2];"
                 :"=r"(r0),"=r"(r1):"r"(a));
}
__device__ __forceinline__ void mma16816(float* c, const uint32_t* a, uint32_t b0, uint32_t b1){
    asm volatile("mma.sync.aligned.m16n8k16.row.col.f32.f16.f16.f32 "
                 "{%0,%1,%2,%3},{%4,%5,%6,%7},{%8,%9},{%0,%1,%2,%3};"
                 :"+f"(c[0]),"+f"(c[1]),"+f"(c[2]),"+f"(c[3])
                 :"r"(a[0]),"r"(a[1]),"r"(a[2]),"r"(a[3]),"r"(b0),"r"(b1));
}
__device__ __forceinline__ void mma16816_z(float* d, const uint32_t* a, uint32_t b0, uint32_t b1){
    asm volatile("mma.sync.aligned.m16n8k16.row.col.f32.f16.f16.f32 "
                 "{%0,%1,%2,%3},{%4,%5,%6,%7},{%8,%9},{%10,%11,%12,%13};"
                 :"=f"(d[0]),"=f"(d[1]),"=f"(d[2]),"=f"(d[3])
                 :"r"(a[0]),"r"(a[1]),"r"(a[2]),"r"(a[3]),"r"(b0),"r"(b1),
                  "f"(0.f),"f"(0.f),"f"(0.f),"f"(0.f));
}
__device__ __forceinline__ void split3(float x, __half& h, __half& m, __half& l){
    h = __float2half_rn(x);
    float r1 = x - __half2float(h);
    m = __float2half_rn(r1 * SPL);
    float r2 = r1 - __half2float(m) * SPLI;
    l = __float2half_rn(r2 * (SPL * SPL));
}

struct Acc { float hh[2][4][4]; float x1[2][4][4]; float x2[2][4][4]; };
__device__ __forceinline__ float comb(const Acc& a, int mt,int nt,int ci){
    return fmaf(SPLI, fmaf(SPLI, a.x2[mt][nt][ci], a.x1[mt][nt][ci]), a.hh[mt][nt][ci]);
}

// ---- double-buffered mainloop over pre-split fp16 operands ----
// LV=3: full 6-mma (gemm1/gemm3); LV=2: hh+hm+mh 3-mma (dist; rescore covers)
template<int KCH, bool EXACT, int LV>
__device__ __forceinline__ void gemm_run(
    const __half* __restrict__ Ah, const __half* __restrict__ Am, const __half* __restrict__ Al, int aK,
    const __half* __restrict__ Bh, const __half* __restrict__ Bm, const __half* __restrict__ Bl, int bK,
    uint32_t sb, int tid, int lane, int warpR0, int warpC0, Acc& ac)
{
    #pragma unroll
    for (int mt=0;mt<2;mt++)
        #pragma unroll
        for (int nt=0;nt<4;nt++)
            #pragma unroll
            for (int ci=0;ci<4;ci++){ ac.hh[mt][nt][ci]=0.f; ac.x1[mt][nt][ci]=0.f; ac.x2[mt][nt][ci]=0.f; }

    const uint32_t aro = (uint32_t)((warpR0 + (lane&15))*144 + (lane>>4)*16);
    const uint32_t bro = (uint32_t)((warpC0 + (lane&7))*144 + ((lane>>3)&1)*16);

    auto stage = [&](int c){
        uint32_t bufb = sb + (uint32_t)(c&1)*BUFB;
        const int kc = c*64;
        #pragma unroll
        for (int s=0;s<4;s++){
            int f = tid + 256*s, r = f>>3, j = f&7;
            uint32_t o = bufb + (uint32_t)(r*144 + j*16);
            const size_t src = (size_t)r*aK + kc + j*8;
            cp16(o + AHs, Ah + src);
            cp16(o + AMs, Am + src);
            if (LV==3) cp16(o + ALs, Al + src);
        }
        #pragma unroll
        for (int s=0;s<2;s++){
            int f = tid + 256*s, r = f>>3, j = f&7;
            uint32_t o = bufb + (uint32_t)(r*144 + j*16);
            const size_t src = (size_t)r*bK + kc + j*8;
            cp16(o + BHs, Bh + src);
            cp16(o + BMs, Bm + src);
            if (LV==3) cp16(o + BLs, Bl + src);
        }
        asm volatile("cp.async.commit_group;");
    };

    stage(0);
    for (int c=0;c<KCH;c++){
        if (c+1<KCH){ stage(c+1); asm volatile("cp.async.wait_group 1;"); }
        else asm volatile("cp.async.wait_group 0;");
        __syncthreads();
        uint32_t bufb = sb + (uint32_t)(c&1)*BUFB;
        #pragma unroll
        for (int kt=0;kt<4;kt++){
            uint32_t ah[2][4], am[2][4], al[2][4];
            #pragma unroll
            for (int mt=0;mt<2;mt++){
                ldsm4(ah[mt], bufb + AHs + aro + mt*2304 + kt*32);
                ldsm4(am[mt], bufb + AMs + aro + mt*2304 + kt*32);
                if (LV==3) ldsm4(al[mt], bufb + ALs + aro + mt*2304 + kt*32);
            }
            #pragma unroll
            for (int nt=0;nt<4;nt++){
                uint32_t bh0,bh1,bm0,bm1,bl0,bl1;
                ldsm2(bh0,bh1, bufb + BHs + bro + nt*1152 + kt*32);
                ldsm2(bm0,bm1, bufb + BMs + bro + nt*1152 + kt*32);
                if (LV==3) ldsm2(bl0,bl1, bufb + BLs + bro + nt*1152 + kt*32);
                #pragma unroll
                for (int mt=0;mt<2;mt++){
                    if (EXACT){
                        float t[4];
                        mma16816_z(t, ah[mt], bh0, bh1);
                        #pragma unroll
                        for (int ci=0;ci<4;ci++) ac.hh[mt][nt][ci] += t[ci];
                    } else {
                        mma16816(ac.hh[mt][nt], ah[mt], bh0, bh1);
                    }
                    mma16816(ac.x1[mt][nt], ah[mt], bm0, bm1);
                    mma16816(ac.x1[mt][nt], am[mt], bh0, bh1);
                    if (LV==3){
                        mma16816(ac.x2[mt][nt], am[mt], bm0, bm1);
                        mma16816(ac.x2[mt][nt], ah[mt], bl0, bl1);
                        mma16816(ac.x2[mt][nt], al[mt], bh0, bh1);
                    }
                }
            }
        }
        __syncthreads();
    }
}

// ---- prep ----
__global__ void k_prep_misc(const float* __restrict__ cb){
    int idx = blockIdx.x*blockDim.x + threadIdx.x;
    if (idx==0) g_loss = 0.0;
    const float* row = cb + (long)idx*Dd; float s=0.f;
    #pragma unroll 8
    for (int d=0; d<Dd; d++) s = fmaf(row[d], row[d], s);
    g_c2[idx] = s;
}
__global__ void k_prep_z(const float* __restrict__ z){
    size_t idx = (size_t)blockIdx.x*256 + threadIdx.x;
    __half h,m,l; split3(z[idx], h, m, l);
    g_rH[idx]=h; g_rM[idx]=m; g_rL[idx]=l;
}
__global__ void k_prep_wi(const float* __restrict__ Wi){
    int idx = blockIdx.x*256 + threadIdx.x;
    int n = idx & 255, k = (idx>>8) & 1023, i = idx>>18;
    __half h,m,l; split3(Wi[idx], h, m, l);
    size_t o = ((size_t)i*Dd + n)*Cc + k;
    g_WiH[o]=h; g_WiM[o]=m; g_WiL[o]=l;
}
__global__ void k_prep_cb(const float* __restrict__ cb){
    int idx = blockIdx.x*256 + threadIdx.x;
    __half h,m,l; split3(cb[idx], h, m, l);
    g_cbH[idx]=h; g_cbM[idx]=m; g_cbL[idx]=l;
}
__global__ void k_prep_wo(const float* __restrict__ Wo){
    int idx = blockIdx.x*256 + threadIdx.x;
    int n = idx & 1023, k = (idx>>10) & 255, i = idx>>18;
    __half h,m,l; split3(Wo[idx], h, m, l);
    size_t o = ((size_t)i*Cc + n)*Dd + k;
    g_WoH[o]=h; g_WoM[o]=m; g_WoL[o]=l;
}

// ---- GEMM1: z_e = resid @ Wi + bi (writes fp32 ze + split fp16 ze) ----
__global__ __launch_bounds__(256,1) void k_gemm1(const float* __restrict__ bi_i,
        float* __restrict__ out, int fo, int icb){
    extern __shared__ __align__(16) char sm[];
    uint32_t sb = smem_u32(sm);
    int tid=threadIdx.x, lane=tid&31, warp=tid>>5;
    int warpR0=(warp&3)*32, warpC0=(warp>>2)*32;
    long m0 = (long)blockIdx.x*128; int n0 = blockIdx.y*64;
    size_t ao = (size_t)m0*Cc;
    size_t bo_ = ((size_t)icb*Dd + n0)*Cc;
    Acc ac;
    gemm_run<16,true,3>(g_rH+ao, g_rM+ao, g_rL+ao, Cc,
                        g_WiH+bo_, g_WiM+bo_, g_WiL+bo_, Cc,
                        sb, tid, lane, warpR0, warpC0, ac);
    int tr = lane>>2, tc = (lane&3)*2;
    #pragma unroll
    for (int mt=0;mt<2;mt++)
    #pragma unroll
    for (int hv=0;hv<2;hv++){
        long gr = m0 + warpR0 + mt*16 + tr + 8*hv;
        #pragma unroll
        for (int nt=0;nt<4;nt++){
            int cg = n0 + warpC0 + nt*8 + tc;
            float v0 = comb(ac,mt,nt,hv*2+0) + bi_i[cg];
            float v1 = comb(ac,mt,nt,hv*2+1) + bi_i[cg+1];
            size_t zo = (size_t)gr*Dd + cg;
            *(float2*)(g_ze + zo) = make_float2(v0, v1);
            __half h0,mm0,l0,h1,mm1,l1;
            split3(v0,h0,mm0,l0); split3(v1,h1,mm1,l1);
            *(__half2*)(g_zeH + zo) = __halves2half2(h0,h1);
            *(__half2*)(g_zeM + zo) = __halves2half2(mm0,mm1);
            *(__half2*)(g_zeL + zo) = __halves2half2(l0,l1);
            if (fo){
                long o = LAT_OFF + gr*(long)(NCB*Dd) + (long)icb*Dd + cg;
                out[o] = v0; out[o+1] = v1;
            }
        }
    }
}

// ---- zsq ----
__global__ void k_zsq(){
    int warp = threadIdx.x>>5, lane = threadIdx.x&31;
    long row = (long)blockIdx.x*8 + warp;
    const float* p = g_ze + row*Dd;
    float s = 0.f;
    #pragma unroll
    for (int j=0;j<8;j++){ float v = p[lane + 32*j]; s = fmaf(v,v,s); }
    #pragma unroll
    for (int off=16; off; off>>=1) s += __shfl_down_sync(0xffffffffu, s, off);
    if (lane==0) g_zsq[row] = s;
}

// ---- DIST: 2-split TC distances -> top-2 candidates per (row, 32-code half) ----
__global__ __launch_bounds__(256,1) void k_dist(int icb){
    extern __shared__ __align__(16) char sm[];
    uint32_t sb = smem_u32(sm);
    int tid=threadIdx.x, lane=tid&31, warp=tid>>5;
    int colg = warp>>2;
    int warpR0=(warp&3)*32, warpC0=colg*32;
    long m0 = (long)blockIdx.x*128; int n0 = blockIdx.y*64;
    size_t ao = (size_t)m0*Dd;
    size_t bo_ = ((size_t)icb*Kk + n0)*Dd;
    Acc ac;
    gemm_run<4,false,2>(g_zeH+ao, g_zeM+ao, (const __half*)nullptr, Dd,
                        g_cbH+bo_, g_cbM+bo_, (const __half*)nullptr, Dd,
                        sb, tid, lane, warpR0, warpC0, ac);
    const float* c2p = g_c2 + icb*Kk;
    int tr = lane>>2, tc = (lane&3)*2;
    const int slot0 = (blockIdx.y*2 + colg)*2;
    #pragma unroll
    for (int mt=0;mt<2;mt++)
    #pragma unroll
    for (int hv=0;hv<2;hv++){
        long gr = m0 + warpR0 + mt*16 + tr + 8*hv;
        float zs = g_zsq[gr];
        float dvv[8]; int cgg[8];
        #pragma unroll
        for (int nt=0;nt<4;nt++)
            #pragma unroll
            for (int jj=0;jj<2;jj++){
                int q = nt*2+jj;
                cgg[q] = n0 + warpC0 + nt*8 + tc + jj;
                dvv[q] = (zs - 2.0f*comb(ac,mt,nt,hv*2+jj)) + c2p[cgg[q]];
            }
        float m1v = dvv[0]; int m1i = cgg[0];
        #pragma unroll
        for (int q=1;q<8;q++) if (dvv[q] < m1v || (dvv[q]==m1v && cgg[q]<m1i)){ m1v=dvv[q]; m1i=cgg[q]; }
        #pragma unroll
        for (int off=1; off<4; off<<=1){
            float ov = __shfl_xor_sync(0xffffffffu, m1v, off);
            int   oi = __shfl_xor_sync(0xffffffffu, m1i, off);
            if (ov < m1v || (ov == m1v && oi < m1i)){ m1v=ov; m1i=oi; }
        }
        float m2v = __int_as_float(0x7f800000); int m2i = 0x7fffffff;
        #pragma unroll
        for (int q=0;q<8;q++)
            if (cgg[q]!=m1i && (dvv[q] < m2v || (dvv[q]==m2v && cgg[q]<m2i))){ m2v=dvv[q]; m2i=cgg[q]; }
        #pragma unroll
        for (int off=1; off<4; off<<=1){
            float ov = __shfl_xor_sync(0xffffffffu, m2v, off);
            int   oi = __shfl_xor_sync(0xffffffffu, m2i, off);
            if (ov < m2v || (ov == m2v && oi < m2i)){ m2v=ov; m2i=oi; }
        }
        if ((lane&3)==0){
            g_cand[gr*128 + slot0 + 0] = ((ull)__float_as_uint(m1v)<<32) | (unsigned)m1i;
            g_cand[gr*128 + slot0 + 1] = ((ull)__float_as_uint(m2v)<<32) | (unsigned)m2i;
        }
    }
}

// ---- PICK: exact fp32 rescore; warp per row ----
__global__ __launch_bounds__(256) void k_pick(const float* __restrict__ cb, int icb){
    int warp = threadIdx.x>>5, lane = threadIdx.x&31;
    long row = (long)blockIdx.x*8 + warp;
    ull cc[4];
    #pragma unroll
    for (int s=0;s<4;s++) cc[s] = g_cand[row*128 + lane*4 + s];
    float mv = __int_as_float(0x7f800000);
    #pragma unroll
    for (int s=0;s<4;s++) mv = fminf(mv, __uint_as_float((uint32_t)(cc[s]>>32)));
    #pragma unroll
    for (int off=16; off; off>>=1) mv = fminf(mv, __shfl_xor_sync(0xffffffffu, mv, off));
    float thr = mv + MARGIN;
    const float* zep = g_ze + row*Dd;
    float zs = g_zsq[row];
    const float* c2p = g_c2 + icb*Kk;
    float bde = __int_as_float(0x7f800000); int bcg = 0x7fffffff;
    #pragma unroll
    for (int s=0;s<4;s++){
        float dv = __uint_as_float((uint32_t)(cc[s]>>32));
        int cg = (int)(cc[s] & 0xffffffffu);
        if (dv <= thr){
            const float* cbp = cb + ((long)icb*Kk + cg)*Dd;
            float dot = 0.f;
            #pragma unroll 8
            for (int j=0;j<64;j++){
                float4 a = *(const float4*)(zep + 4*j);
                float4 b = __ldg((const float4*)(cbp + 4*j));
                dot = fmaf(a.x,b.x,dot); dot = fmaf(a.y,b.y,dot);
                dot = fmaf(a.z,b.z,dot); dot = fmaf(a.w,b.w,dot);
            }
            float de = (zs - 2.0f*dot) + c2p[cg];
            if (de < bde || (de == bde && cg < bcg)){ bde = de; bcg = cg; }
        }
    }
    #pragma unroll
    for (int off=16; off; off>>=1){
        float od = __shfl_xor_sync(0xffffffffu, bde, off);
        int   oc = __shfl_xor_sync(0xffffffffu, bcg, off);
        if (od < bde || (od == bde && oc < bcg)){ bde = od; bcg = oc; }
    }
    if (lane==0) g_idx[row] = bcg;
}

// ---- GATHER: q (fp32 + split fp16), commit loss, codes ----
__global__ __launch_bounds__(256) void k_gather(const float* __restrict__ cb,
        float* __restrict__ out, int fo, int icb){
    int tid = threadIdx.x, lane = tid&31, warp = tid>>5;
    long gid = (long)blockIdx.x*256 + tid;
    long row = gid >> 2; int seg = (int)(gid & 3) * 64;
    int code = g_idx[row];
    const float* ep = cb + ((long)icb*Kk + code)*Dd + seg;
    float* zp = g_ze + row*Dd + seg;
    size_t zo = (size_t)row*Dd + seg;
    float lp = 0.f;
    #pragma unroll
    for (int j=0;j<16;j++){
        float4 ze4 = *(const float4*)(zp + 4*j);
        float4 e4  = *(const float4*)(ep + 4*j);
        float d0 = ze4.x-e4.x, d1 = ze4.y-e4.y, d2 = ze4.z-e4.z, d3 = ze4.w-e4.w;
        lp = fmaf(d0,d0,fmaf(d1,d1,fmaf(d2,d2,fmaf(d3,d3,lp))));
        float q0 = ze4.x+(e4.x-ze4.x), q1 = ze4.y+(e4.y-ze4.y);
        float q2 = ze4.z+(e4.z-ze4.z), q3 = ze4.w+(e4.w-ze4.w);
        *(float4*)(zp + 4*j) = make_float4(q0,q1,q2,q3);
        __half h0,m0,l0,h1,m1,l1,h2,m2,l2,h3,m3,l3;
        split3(q0,h0,m0,l0); split3(q1,h1,m1,l1);
        split3(q2,h2,m2,l2); split3(q3,h3,m3,l3);
        *(__half2*)(g_zeH + zo + 4*j)     = __halves2half2(h0,h1);
        *(__half2*)(g_zeH + zo + 4*j + 2) = __halves2half2(h2,h3);
        *(__half2*)(g_zeM + zo + 4*j)     = __halves2half2(m0,m1);
        *(__half2*)(g_zeM + zo + 4*j + 2) = __halves2half2(m2,m3);
        *(__half2*)(g_zeL + zo + 4*j)     = __halves2half2(l0,l1);
        *(__half2*)(g_zeL + zo + 4*j + 2) = __halves2half2(l2,l3);
    }
    if (fo && (gid&3)==0) out[CODE_OFF + row*NCB + icb] = (float)code;
    #pragma unroll
    for (int off=16; off; off>>=1) lp += __shfl_down_sync(0xffffffffu, lp, off);
    __shared__ float wr[8];
    if (lane==0) wr[warp] = lp;
    __syncthreads();
    if (tid==0){ float s=0.f; for (int w=0;w<8;w++) s += wr[w]; atomicAdd(&g_loss, (double)s); }
}

// ---- GEMM3: resid -= q @ Wo + bo (writes fp32 resid + splits); last: z_q ----
__global__ __launch_bounds__(256,1) void k_gemm3(const float* __restrict__ z,
        const float* __restrict__ bo_i, float* __restrict__ out, int icb){
    extern __shared__ __align__(16) char sm[];
    uint32_t sb = smem_u32(sm);
    int tid=threadIdx.x, lane=tid&31, warp=tid>>5;
    int warpR0=(warp&3)*32, warpC0=(warp>>2)*32;
    long m0 = (long)blockIdx.x*128; int n0 = blockIdx.y*64;
    size_t ao = (size_t)m0*Dd;
    size_t bo_ = ((size_t)icb*Cc + n0)*Dd;
    Acc ac;
    gemm_run<4,true,3>(g_zeH+ao, g_zeM+ao, g_zeL+ao, Dd,
                       g_WoH+bo_, g_WoM+bo_, g_WoL+bo_, Dd,
                       sb, tid, lane, warpR0, warpC0, ac);
    const float* rsrc = (icb ? g_resid : z);
    const int last = (icb == NCB-1);
    int tr = lane>>2, tc = (lane&3)*2;
    #pragma unroll
    for (int mt=0;mt<2;mt++)
    #pragma unroll
    for (int hv=0;hv<2;hv++){
        long gr = m0 + warpR0 + mt*16 + tr + 8*hv;
        #pragma unroll
        for (int nt=0;nt<4;nt++){
            int cg = n0 + warpC0 + nt*8 + tc;
            float v0 = comb(ac,mt,nt,hv*2+0) + bo_i[cg];
            float v1 = comb(ac,mt,nt,hv*2+1) + bo_i[cg+1];
            size_t ro = (size_t)gr*Cc + cg;
            float2 rv = *(const float2*)(rsrc + ro);
            float nr0 = rv.x - v0, nr1 = rv.y - v1;
            if (last){
                float2 zz = *(const float2*)(z + ro);
                *(float2*)(out + ro) = make_float2(zz.x - nr0, zz.y - nr1);
            } else {
                *(float2*)(g_resid + ro) = make_float2(nr0, nr1);
                __half h0,m0h,l0,h1,m1h,l1;
                split3(nr0,h0,m0h,l0); split3(nr1,h1,m1h,l1);
                *(__half2*)(g_rH + ro) = __halves2half2(h0,h1);
                *(__half2*)(g_rM + ro) = __halves2half2(m0h,m1h);
                *(__half2*)(g_rL + ro) = __halves2half2(l0,l1);
            }
        }
    }
}

__global__ void k_fin(float* __restrict__ out, int fo){
    if (fo && threadIdx.x==0){
        double t = g_loss;
        float enc = (float)(0.25 * t / ((double)Bn * (double)Dd));
        out[SC_OFF+0] = enc; out[SC_OFF+1] = enc; out[SC_OFF+2] = 0.f;
    }
}

extern "C" void kernel_launch(void* const* d_in, const int* in_sizes, int n_in,
                              void* d_out, int out_size) {
    const float* z  = (const float*)d_in[0];
    const float* cb = (const float*)d_in[1];
    const float* Wi = (const float*)d_in[2];
    const float* bi = (const float*)d_in[3];
    const float* Wo = (const float*)d_in[4];
    const float* bo = (const float*)d_in[5];
    float* out = (float*)d_out;
    const int fo = ((long)out_size > SC_OFF) ? 1 : 0;

    cudaFuncSetAttribute(k_gemm1, cudaFuncAttributeMaxDynamicSharedMemorySize, SMEMB);
    cudaFuncSetAttribute(k_dist,  cudaFuncAttributeMaxDynamicSharedMemorySize, SMEMB);
    cudaFuncSetAttribute(k_gemm3, cudaFuncAttributeMaxDynamicSharedMemorySize, SMEMB);

    k_prep_misc<<<NCB*Kk/256, 256>>>(cb);
    k_prep_z<<<(int)(((size_t)Bn*Cc)/256), 256>>>(z);
    k_prep_wi<<<(NCB*Cc*Dd)/256, 256>>>(Wi);
    k_prep_cb<<<(NCB*Kk*Dd)/256, 256>>>(cb);
    k_prep_wo<<<(NCB*Dd*Cc)/256, 256>>>(Wo);

    for (int i=0;i<NCB;i++){
        k_gemm1<<<dim3(512,4), 256, SMEMB>>>(bi + i*Dd, out, fo, i);
        k_zsq<<<Bn/8, 256>>>();
        k_dist<<<dim3(512,32), 256, SMEMB>>>(i);
        k_pick<<<Bn/8, 256>>>(cb, i);
        k_gather<<<Bn*4/256, 256>>>(cb, out, fo, i);
        k_gemm3<<<dim3(512,16), 256, SMEMB>>>(z, bo + i*Cc, out, i);
    }
    k_fin<<<1, 32>>>(out, fo);
}

// round 16
// speedup vs baseline: 1.9541x; 1.0898x over previous
#include <cuda_runtime.h>
#include <cuda_fp16.h>
#include <cstdint>

typedef unsigned long long ull;
constexpr int Bn=65536, Cc=1024, Dd=256, Kk=2048, NCB=4;
constexpr long SC_OFF=(long)Bn*Cc, CODE_OFF=SC_OFF+3, LAT_OFF=CODE_OFF+(long)Bn*NCB;
constexpr float SPL = 2048.f, SPLI = 1.f/2048.f;
constexpr float MARGIN = 1e-3f;

// gemm1/gemm3 smem (double-buffered, LV3)
constexpr uint32_t AHs=0, AMs=18432, ALs=36864;
constexpr uint32_t BHs=55296, BMs=64512, BLs=73728;
constexpr uint32_t BUFB=82944, SMEMB=2*BUFB;   // 165888

// dist smem: resident A (2 splits, 128 x 528B) + double-buffered B (64 x 272B x 2 splits)
constexpr uint32_t D_AH=0, D_AM=67584;
constexpr uint32_t D_B0=135168, D_BSZ=34816;   // within buf: BH +0, BM +17408
constexpr uint32_t D_SMEMB=204800;

// ---- static scratch ----
__device__ float g_resid[(size_t)Bn*Cc];
__device__ float g_ze[(size_t)Bn*Dd];
__device__ float g_zsq[Bn];
__device__ int   g_idx[Bn];
__device__ ull   g_cand[(size_t)Bn*128];
__device__ float g_c2[NCB*Kk];
__device__ double g_loss;
__device__ __align__(128) __half g_rH[(size_t)Bn*Cc];
__device__ __align__(128) __half g_rM[(size_t)Bn*Cc];
__device__ __align__(128) __half g_rL[(size_t)Bn*Cc];
__device__ __align__(128) __half g_zeH[(size_t)Bn*Dd];
__device__ __align__(128) __half g_zeM[(size_t)Bn*Dd];
__device__ __align__(128) __half g_zeL[(size_t)Bn*Dd];
__device__ __align__(128) __half g_WiH[(size_t)NCB*Dd*Cc];
__device__ __align__(128) __half g_WiM[(size_t)NCB*Dd*Cc];
__device__ __align__(128) __half g_WiL[(size_t)NCB*Dd*Cc];
__device__ __align__(128) __half g_cbH[(size_t)NCB*Kk*Dd];
__device__ __align__(128) __half g_cbM[(size_t)NCB*Kk*Dd];
__device__ __align__(128) __half g_cbL[(size_t)NCB*Kk*Dd];
__device__ __align__(128) __half g_WoH[(size_t)NCB*Cc*Dd];
__device__ __align__(128) __half g_WoM[(size_t)NCB*Cc*Dd];
__device__ __align__(128) __half g_WoL[(size_t)NCB*Cc*Dd];

// ---- helpers ----
__device__ __forceinline__ uint32_t smem_u32(const void* p){
    uint32_t a; asm("{ .reg .u64 t; cvta.to.shared.u64 t, %1; cvt.u32.u64 %0, t; }":"=r"(a):"l"(p)); return a;
}
__device__ __forceinline__ void cp16(uint32_t d, const void* s){
    asm volatile("cp.async.cg.shared.global [%0], [%1], 16;"::"r"(d),"l"(s));
}
__device__ __forceinline__ void ldsm4(uint32_t* r, uint32_t a){
    asm volatile("ldmatrix.sync.aligned.m8n8.x4.shared.b16 {%0,%1,%2,%3}, [%4];"
                 :"=r"(r[0]),"=r"(r[1]),"=r"(r[2]),"=r"(r[3]):"r"(a));
}
__device__ __forceinline__ void ldsm2(uint32_t& r0,uint32_t& r1, uint32_t a){
    asm volatile("ldmatrix.sync.aligned.m8n8.x2.shared.b16 {%0,%1}, [%2];"
                 :"=r"(r0),"=r"(r1):"r"(a));
}
__device__ __forceinline__ void mma16816(float* c, const uint32_t* a, uint32_t b0, uint32_t b1){
    asm volatile("mma.sync.aligned.m16n8k16.row.col.f32.f16.f16.f32 "
                 "{%0,%1,%2,%3},{%4,%5,%6,%7},{%8,%9},{%0,%1,%2,%3};"
                 :"+f"(c[0]),"+f"(c[1]),"+f"(c[2]),"+f"(c[3])
                 :"r"(a[0]),"r"(a[1]),"r"(a[2]),"r"(a[3]),"r"(b0),"r"(b1));
}
__device__ __forceinline__ void mma16816_z(float* d, const uint32_t* a, uint32_t b0, uint32_t b1){
    asm volatile("mma.sync.aligned.m16n8k16.row.col.f32.f16.f16.f32 "
                 "{%0,%1,%2,%3},{%4,%5,%6,%7},{%8,%9},{%10,%11,%12,%13};"
                 :"=f"(d[0]),"=f"(d[1]),"=f"(d[2]),"=f"(d[3])
                 :"r"(a[0]),"r"(a[1]),"r"(a[2]),"r"(a[3]),"r"(b0),"r"(b1),
                  "f"(0.f),"f"(0.f),"f"(0.f),"f"(0.f));
}
__device__ __forceinline__ void split3(float x, __half& h, __half& m, __half& l){
    h = __float2half_rn(x);
    float r1 = x - __half2float(h);
    m = __float2half_rn(r1 * SPL);
    float r2 = r1 - __half2float(m) * SPLI;
    l = __float2half_rn(r2 * (SPL * SPL));
}

struct Acc { float hh[2][4][4]; float x1[2][4][4]; float x2[2][4][4]; };
__device__ __forceinline__ float comb(const Acc& a, int mt,int nt,int ci){
    return fmaf(SPLI, fmaf(SPLI, a.x2[mt][nt][ci], a.x1[mt][nt][ci]), a.hh[mt][nt][ci]);
}

// ---- double-buffered mainloop (gemm1/gemm3, 3-split, exact hh) ----
template<int KCH, bool EXACT>
__device__ __forceinline__ void gemm_run(
    const __half* __restrict__ Ah, const __half* __restrict__ Am, const __half* __restrict__ Al, int aK,
    const __half* __restrict__ Bh, const __half* __restrict__ Bm, const __half* __restrict__ Bl, int bK,
    uint32_t sb, int tid, int lane, int warpR0, int warpC0, Acc& ac)
{
    #pragma unroll
    for (int mt=0;mt<2;mt++)
        #pragma unroll
        for (int nt=0;nt<4;nt++)
            #pragma unroll
            for (int ci=0;ci<4;ci++){ ac.hh[mt][nt][ci]=0.f; ac.x1[mt][nt][ci]=0.f; ac.x2[mt][nt][ci]=0.f; }

    const uint32_t aro = (uint32_t)((warpR0 + (lane&15))*144 + (lane>>4)*16);
    const uint32_t bro = (uint32_t)((warpC0 + (lane&7))*144 + ((lane>>3)&1)*16);

    auto stage = [&](int c){
        uint32_t bufb = sb + (uint32_t)(c&1)*BUFB;
        const int kc = c*64;
        #pragma unroll
        for (int s=0;s<4;s++){
            int f = tid + 256*s, r = f>>3, j = f&7;
            uint32_t o = bufb + (uint32_t)(r*144 + j*16);
            const size_t src = (size_t)r*aK + kc + j*8;
            cp16(o + AHs, Ah + src);
            cp16(o + AMs, Am + src);
            cp16(o + ALs, Al + src);
        }
        #pragma unroll
        for (int s=0;s<2;s++){
            int f = tid + 256*s, r = f>>3, j = f&7;
            uint32_t o = bufb + (uint32_t)(r*144 + j*16);
            const size_t src = (size_t)r*bK + kc + j*8;
            cp16(o + BHs, Bh + src);
            cp16(o + BMs, Bm + src);
            cp16(o + BLs, Bl + src);
        }
        asm volatile("cp.async.commit_group;");
    };

    stage(0);
    for (int c=0;c<KCH;c++){
        if (c+1<KCH){ stage(c+1); asm volatile("cp.async.wait_group 1;"); }
        else asm volatile("cp.async.wait_group 0;");
        __syncthreads();
        uint32_t bufb = sb + (uint32_t)(c&1)*BUFB;
        #pragma unroll
        for (int kt=0;kt<4;kt++){
            uint32_t ah[2][4], am[2][4], al[2][4];
            #pragma unroll
            for (int mt=0;mt<2;mt++){
                ldsm4(ah[mt], bufb + AHs + aro + mt*2304 + kt*32);
                ldsm4(am[mt], bufb + AMs + aro + mt*2304 + kt*32);
                ldsm4(al[mt], bufb + ALs + aro + mt*2304 + kt*32);
            }
            #pragma unroll
            for (int nt=0;nt<4;nt++){
                uint32_t bh0,bh1,bm0,bm1,bl0,bl1;
                ldsm2(bh0,bh1, bufb + BHs + bro + nt*1152 + kt*32);
                ldsm2(bm0,bm1, bufb + BMs + bro + nt*1152 + kt*32);
                ldsm2(bl0,bl1, bufb + BLs + bro + nt*1152 + kt*32);
                #pragma unroll
                for (int mt=0;mt<2;mt++){
                    if (EXACT){
                        float t[4];
                        mma16816_z(t, ah[mt], bh0, bh1);
                        #pragma unroll
                        for (int ci=0;ci<4;ci++) ac.hh[mt][nt][ci] += t[ci];
                    } else {
                        mma16816(ac.hh[mt][nt], ah[mt], bh0, bh1);
                    }
                    mma16816(ac.x1[mt][nt], ah[mt], bm0, bm1);
                    mma16816(ac.x1[mt][nt], am[mt], bh0, bh1);
                    mma16816(ac.x2[mt][nt], am[mt], bm0, bm1);
                    mma16816(ac.x2[mt][nt], ah[mt], bl0, bl1);
                    mma16816(ac.x2[mt][nt], al[mt], bh0, bh1);
                }
            }
        }
        __syncthreads();
    }
}

// ---- prep ----
__global__ void k_prep_misc(const float* __restrict__ cb){
    int idx = blockIdx.x*blockDim.x + threadIdx.x;
    if (idx==0) g_loss = 0.0;
    const float* row = cb + (long)idx*Dd; float s=0.f;
    #pragma unroll 8
    for (int d=0; d<Dd; d++) s = fmaf(row[d], row[d], s);
    g_c2[idx] = s;
}
__global__ void k_prep_z(const float* __restrict__ z){
    size_t idx = (size_t)blockIdx.x*256 + threadIdx.x;
    __half h,m,l; split3(z[idx], h, m, l);
    g_rH[idx]=h; g_rM[idx]=m; g_rL[idx]=l;
}
__global__ void k_prep_wi(const float* __restrict__ Wi){
    int idx = blockIdx.x*256 + threadIdx.x;
    int n = idx & 255, k = (idx>>8) & 1023, i = idx>>18;
    __half h,m,l; split3(Wi[idx], h, m, l);
    size_t o = ((size_t)i*Dd + n)*Cc + k;
    g_WiH[o]=h; g_WiM[o]=m; g_WiL[o]=l;
}
__global__ void k_prep_cb(const float* __restrict__ cb){
    int idx = blockIdx.x*256 + threadIdx.x;
    __half h,m,l; split3(cb[idx], h, m, l);
    g_cbH[idx]=h; g_cbM[idx]=m; g_cbL[idx]=l;
}
__global__ void k_prep_wo(const float* __restrict__ Wo){
    int idx = blockIdx.x*256 + threadIdx.x;
    int n = idx & 1023, k = (idx>>10) & 255, i = idx>>18;
    __half h,m,l; split3(Wo[idx], h, m, l);
    size_t o = ((size_t)i*Cc + n)*Dd + k;
    g_WoH[o]=h; g_WoM[o]=m; g_WoL[o]=l;
}

// ---- GEMM1: z_e = resid @ Wi + bi ----
__global__ __launch_bounds__(256,1) void k_gemm1(const float* __restrict__ bi_i,
        float* __restrict__ out, int fo, int icb){
    extern __shared__ __align__(16) char sm[];
    uint32_t sb = smem_u32(sm);
    int tid=threadIdx.x, lane=tid&31, warp=tid>>5;
    int warpR0=(warp&3)*32, warpC0=(warp>>2)*32;
    long m0 = (long)blockIdx.x*128; int n0 = blockIdx.y*64;
    size_t ao = (size_t)m0*Cc;
    size_t bo_ = ((size_t)icb*Dd + n0)*Cc;
    Acc ac;
    gemm_run<16,true>(g_rH+ao, g_rM+ao, g_rL+ao, Cc,
                      g_WiH+bo_, g_WiM+bo_, g_WiL+bo_, Cc,
                      sb, tid, lane, warpR0, warpC0, ac);
    int tr = lane>>2, tc = (lane&3)*2;
    #pragma unroll
    for (int mt=0;mt<2;mt++)
    #pragma unroll
    for (int hv=0;hv<2;hv++){
        long gr = m0 + warpR0 + mt*16 + tr + 8*hv;
        #pragma unroll
        for (int nt=0;nt<4;nt++){
            int cg = n0 + warpC0 + nt*8 + tc;
            float v0 = comb(ac,mt,nt,hv*2+0) + bi_i[cg];
            float v1 = comb(ac,mt,nt,hv*2+1) + bi_i[cg+1];
            size_t zo = (size_t)gr*Dd + cg;
            *(float2*)(g_ze + zo) = make_float2(v0, v1);
            __half h0,mm0,l0,h1,mm1,l1;
            split3(v0,h0,mm0,l0); split3(v1,h1,mm1,l1);
            *(__half2*)(g_zeH + zo) = __halves2half2(h0,h1);
            *(__half2*)(g_zeM + zo) = __halves2half2(mm0,mm1);
            *(__half2*)(g_zeL + zo) = __halves2half2(l0,l1);
            if (fo){
                long o = LAT_OFF + gr*(long)(NCB*Dd) + (long)icb*Dd + cg;
                out[o] = v0; out[o+1] = v1;
            }
        }
    }
}

// ---- zsq ----
__global__ void k_zsq(){
    int warp = threadIdx.x>>5, lane = threadIdx.x&31;
    long row = (long)blockIdx.x*8 + warp;
    const float* p = g_ze + row*Dd;
    float s = 0.f;
    #pragma unroll
    for (int j=0;j<8;j++){ float v = p[lane + 32*j]; s = fmaf(v,v,s); }
    #pragma unroll
    for (int off=16; off; off>>=1) s += __shfl_down_sync(0xffffffffu, s, off);
    if (lane==0) g_zsq[row] = s;
}

// ---- DIST v2: resident A, internal ntile loop, double-buffered B ----
__global__ __launch_bounds__(256,1) void k_dist(int icb){
    extern __shared__ __align__(16) char sm[];
    uint32_t sb = smem_u32(sm);
    int tid=threadIdx.x, lane=tid&31, warp=tid>>5;
    int colg = warp>>2;
    int warpR0=(warp&3)*32, warpC0=colg*32;
    long m0 = (long)blockIdx.x*128;
    int ntbase = blockIdx.y*16;
    size_t ao = (size_t)m0*Dd;
    const __half* Ah = g_zeH + ao;
    const __half* Am = g_zeM + ao;
    const __half* BhAll = g_cbH + (size_t)icb*Kk*Dd;
    const __half* BmAll = g_cbM + (size_t)icb*Kk*Dd;

    // stage resident A (2 splits): 128 rows x 512B, padded stride 528
    #pragma unroll
    for (int s=0;s<16;s++){
        int f = tid + 256*s, r = f>>5, j = f&31;
        cp16(sb + D_AH + (uint32_t)(r*528 + j*16), Ah + (size_t)r*Dd + j*8);
        cp16(sb + D_AM + (uint32_t)(r*528 + j*16), Am + (size_t)r*Dd + j*8);
    }
    asm volatile("cp.async.commit_group;");

    auto stageB = [&](int ci){
        int nt = ntbase + (ci>>1);
        int kc = (ci&1)*128;
        uint32_t bb = sb + D_B0 + (uint32_t)(ci&1)*D_BSZ;
        size_t base = (size_t)(nt*64)*Dd + kc;
        #pragma unroll
        for (int s=0;s<4;s++){
            int f = tid + 256*s, r = f>>4, j = f&15;
            cp16(bb + (uint32_t)(r*272 + j*16), BhAll + base + (size_t)r*Dd + j*8);
            cp16(bb + 17408u + (uint32_t)(r*272 + j*16), BmAll + base + (size_t)r*Dd + j*8);
        }
        asm volatile("cp.async.commit_group;");
    };
    stageB(0);

    int tr = lane>>2, tc = (lane&3)*2;
    float zsv[2][2];
    #pragma unroll
    for (int mt=0;mt<2;mt++)
        #pragma unroll
        for (int hv=0;hv<2;hv++)
            zsv[mt][hv] = g_zsq[m0 + warpR0 + mt*16 + tr + 8*hv];
    const uint32_t aro = (uint32_t)((warpR0 + (lane&15))*528 + (lane>>4)*16);
    const uint32_t bro = (uint32_t)((warpC0 + (lane&7))*272 + ((lane>>3)&1)*16);
    const float* c2p = g_c2 + icb*Kk;

    for (int nt=0; nt<16; nt++){
        float hh[2][4][4], x1[2][4][4];
        #pragma unroll
        for (int mt=0;mt<2;mt++)
            #pragma unroll
            for (int n2=0;n2<4;n2++)
                #pragma unroll
                for (int ci=0;ci<4;ci++){ hh[mt][n2][ci]=0.f; x1[mt][n2][ci]=0.f; }
        for (int c=0;c<2;c++){
            int ci = nt*2 + c;
            if (ci+1 < 32){ stageB(ci+1); asm volatile("cp.async.wait_group 1;"); }
            else asm volatile("cp.async.wait_group 0;");
            __syncthreads();
            uint32_t bb = sb + D_B0 + (uint32_t)(ci&1)*D_BSZ;
            #pragma unroll
            for (int kt=0;kt<8;kt++){
                int ktg = c*8 + kt;
                uint32_t ah[2][4], am[2][4];
                #pragma unroll
                for (int mt=0;mt<2;mt++){
                    ldsm4(ah[mt], sb + D_AH + aro + mt*8448 + ktg*32);
                    ldsm4(am[mt], sb + D_AM + aro + mt*8448 + ktg*32);
                }
                #pragma unroll
                for (int n2=0;n2<4;n2++){
                    uint32_t bh0,bh1,bm0,bm1;
                    ldsm2(bh0,bh1, bb + bro + n2*2176 + kt*32);
                    ldsm2(bm0,bm1, bb + 17408u + bro + n2*2176 + kt*32);
                    #pragma unroll
                    for (int mt=0;mt<2;mt++){
                        mma16816(hh[mt][n2], ah[mt], bh0, bh1);
                        mma16816(x1[mt][n2], ah[mt], bm0, bm1);
                        mma16816(x1[mt][n2], am[mt], bh0, bh1);
                    }
                }
            }
            __syncthreads();
        }
        // epilogue for this ntile
        int code_b = (ntbase + nt)*64;
        const int slot0 = ((ntbase + nt)*2 + colg)*2;
        #pragma unroll
        for (int mt=0;mt<2;mt++)
        #pragma unroll
        for (int hv=0;hv<2;hv++){
            long gr = m0 + warpR0 + mt*16 + tr + 8*hv;
            float zs = zsv[mt][hv];
            float dvv[8]; int cgg[8];
            #pragma unroll
            for (int n2=0;n2<4;n2++)
                #pragma unroll
                for (int jj=0;jj<2;jj++){
                    int q = n2*2+jj;
                    cgg[q] = code_b + warpC0 + n2*8 + tc + jj;
                    float dot = fmaf(SPLI, x1[mt][n2][hv*2+jj], hh[mt][n2][hv*2+jj]);
                    dvv[q] = (zs - 2.0f*dot) + c2p[cgg[q]];
                }
            float m1v = dvv[0]; int m1i = cgg[0];
            #pragma unroll
            for (int q=1;q<8;q++) if (dvv[q] < m1v || (dvv[q]==m1v && cgg[q]<m1i)){ m1v=dvv[q]; m1i=cgg[q]; }
            #pragma unroll
            for (int off=1; off<4; off<<=1){
                float ov = __shfl_xor_sync(0xffffffffu, m1v, off);
                int   oi = __shfl_xor_sync(0xffffffffu, m1i, off);
                if (ov < m1v || (ov == m1v && oi < m1i)){ m1v=ov; m1i=oi; }
            }
            float m2v = __int_as_float(0x7f800000); int m2i = 0x7fffffff;
            #pragma unroll
            for (int q=0;q<8;q++)
                if (cgg[q]!=m1i && (dvv[q] < m2v || (dvv[q]==m2v && cgg[q]<m2i))){ m2v=dvv[q]; m2i=cgg[q]; }
            #pragma unroll
            for (int off=1; off<4; off<<=1){
                float ov = __shfl_xor_sync(0xffffffffu, m2v, off);
                int   oi = __shfl_xor_sync(0xffffffffu, m2i, off);
                if (ov < m2v || (ov == m2v && oi < m2i)){ m2v=ov; m2i=oi; }
            }
            if ((lane&3)==0){
                g_cand[gr*128 + slot0 + 0] = ((ull)__float_as_uint(m1v)<<32) | (unsigned)m1i;
                g_cand[gr*128 + slot0 + 1] = ((ull)__float_as_uint(m2v)<<32) | (unsigned)m2i;
            }
        }
    }
}

// ---- PICK: exact fp32 rescore; warp per row ----
__global__ __launch_bounds__(256) void k_pick(const float* __restrict__ cb, int icb){
    int warp = threadIdx.x>>5, lane = threadIdx.x&31;
    long row = (long)blockIdx.x*8 + warp;
    ull cc[4];
    #pragma unroll
    for (int s=0;s<4;s++) cc[s] = g_cand[row*128 + lane*4 + s];
    float mv = __int_as_float(0x7f800000);
    #pragma unroll
    for (int s=0;s<4;s++) mv = fminf(mv, __uint_as_float((uint32_t)(cc[s]>>32)));
    #pragma unroll
    for (int off=16; off; off>>=1) mv = fminf(mv, __shfl_xor_sync(0xffffffffu, mv, off));
    float thr = mv + MARGIN;
    const float* zep = g_ze + row*Dd;
    float zs = g_zsq[row];
    const float* c2p = g_c2 + icb*Kk;
    float bde = __int_as_float(0x7f800000); int bcg = 0x7fffffff;
    #pragma unroll
    for (int s=0;s<4;s++){
        float dv = __uint_as_float((uint32_t)(cc[s]>>32));
        int cg = (int)(cc[s] & 0xffffffffu);
        if (dv <= thr){
            const float* cbp = cb + ((long)icb*Kk + cg)*Dd;
            float dot = 0.f;
            #pragma unroll 8
            for (int j=0;j<64;j++){
                float4 a = *(const float4*)(zep + 4*j);
                float4 b = __ldg((const float4*)(cbp + 4*j));
                dot = fmaf(a.x,b.x,dot); dot = fmaf(a.y,b.y,dot);
                dot = fmaf(a.z,b.z,dot); dot = fmaf(a.w,b.w,dot);
            }
            float de = (zs - 2.0f*dot) + c2p[cg];
            if (de < bde || (de == bde && cg < bcg)){ bde = de; bcg = cg; }
        }
    }
    #pragma unroll
    for (int off=16; off; off>>=1){
        float od = __shfl_xor_sync(0xffffffffu, bde, off);
        int   oc = __shfl_xor_sync(0xffffffffu, bcg, off);
        if (od < bde || (od == bde && oc < bcg)){ bde = od; bcg = oc; }
    }
    if (lane==0) g_idx[row] = bcg;
}

// ---- GATHER: q (fp32 + split fp16), commit loss, codes ----
__global__ __launch_bounds__(256) void k_gather(const float* __restrict__ cb,
        float* __restrict__ out, int fo, int icb){
    int tid = threadIdx.x, lane = tid&31, warp = tid>>5;
    long gid = (long)blockIdx.x*256 + tid;
    long row = gid >> 2; int seg = (int)(gid & 3) * 64;
    int code = g_idx[row];
    const float* ep = cb + ((long)icb*Kk + code)*Dd + seg;
    float* zp = g_ze + row*Dd + seg;
    size_t zo = (size_t)row*Dd + seg;
    float lp = 0.f;
    #pragma unroll
    for (int j=0;j<16;j++){
        float4 ze4 = *(const float4*)(zp + 4*j);
        float4 e4  = *(const float4*)(ep + 4*j);
        float d0 = ze4.x-e4.x, d1 = ze4.y-e4.y, d2 = ze4.z-e4.z, d3 = ze4.w-e4.w;
        lp = fmaf(d0,d0,fmaf(d1,d1,fmaf(d2,d2,fmaf(d3,d3,lp))));
        float q0 = ze4.x+(e4.x-ze4.x), q1 = ze4.y+(e4.y-ze4.y);
        float q2 = ze4.z+(e4.z-ze4.z), q3 = ze4.w+(e4.w-ze4.w);
        *(float4*)(zp + 4*j) = make_float4(q0,q1,q2,q3);
        __half h0,m0,l0,h1,m1,l1,h2,m2,l2,h3,m3,l3;
        split3(q0,h0,m0,l0); split3(q1,h1,m1,l1);
        split3(q2,h2,m2,l2); split3(q3,h3,m3,l3);
        *(__half2*)(g_zeH + zo + 4*j)     = __halves2half2(h0,h1);
        *(__half2*)(g_zeH + zo + 4*j + 2) = __halves2half2(h2,h3);
        *(__half2*)(g_zeM + zo + 4*j)     = __halves2half2(m0,m1);
        *(__half2*)(g_zeM + zo + 4*j + 2) = __halves2half2(m2,m3);
        *(__half2*)(g_zeL + zo + 4*j)     = __halves2half2(l0,l1);
        *(__half2*)(g_zeL + zo + 4*j + 2) = __halves2half2(l2,l3);
    }
    if (fo && (gid&3)==0) out[CODE_OFF + row*NCB + icb] = (float)code;
    #pragma unroll
    for (int off=16; off; off>>=1) lp += __shfl_down_sync(0xffffffffu, lp, off);
    __shared__ float wr[8];
    if (lane==0) wr[warp] = lp;
    __syncthreads();
    if (tid==0){ float s=0.f; for (int w=0;w<8;w++) s += wr[w]; atomicAdd(&g_loss, (double)s); }
}

// ---- GEMM3: resid -= q @ Wo + bo ; last: z_q = z - resid ----
__global__ __launch_bounds__(256,1) void k_gemm3(const float* __restrict__ z,
        const float* __restrict__ bo_i, float* __restrict__ out, int icb){
    extern __shared__ __align__(16) char sm[];
    uint32_t sb = smem_u32(sm);
    int tid=threadIdx.x, lane=tid&31, warp=tid>>5;
    int warpR0=(warp&3)*32, warpC0=(warp>>2)*32;
    long m0 = (long)blockIdx.x*128; int n0 = blockIdx.y*64;
    size_t ao = (size_t)m0*Dd;
    size_t bo_ = ((size_t)icb*Cc + n0)*Dd;
    Acc ac;
    gemm_run<4,true>(g_zeH+ao, g_zeM+ao, g_zeL+ao, Dd,
                     g_WoH+bo_, g_WoM+bo_, g_WoL+bo_, Dd,
                     sb, tid, lane, warpR0, warpC0, ac);
    const float* rsrc = (icb ? g_resid : z);
    const int last = (icb == NCB-1);
    int tr = lane>>2, tc = (lane&3)*2;
    #pragma unroll
    for (int mt=0;mt<2;mt++)
    #pragma unroll
    for (int hv=0;hv<2;hv++){
        long gr = m0 + warpR0 + mt*16 + tr + 8*hv;
        #pragma unroll
        for (int nt=0;nt<4;nt++){
            int cg = n0 + warpC0 + nt*8 + tc;
            float v0 = comb(ac,mt,nt,hv*2+0) + bo_i[cg];
            float v1 = comb(ac,mt,nt,hv*2+1) + bo_i[cg+1];
            size_t ro = (size_t)gr*Cc + cg;
            float2 rv = *(const float2*)(rsrc + ro);
            float nr0 = rv.x - v0, nr1 = rv.y - v1;
            if (last){
                float2 zz = *(const float2*)(z + ro);
                *(float2*)(out + ro) = make_float2(zz.x - nr0, zz.y - nr1);
            } else {
                *(float2*)(g_resid + ro) = make_float2(nr0, nr1);
                __half h0,m0h,l0,h1,m1h,l1;
                split3(nr0,h0,m0h,l0); split3(nr1,h1,m1h,l1);
                *(__half2*)(g_rH + ro) = __halves2half2(h0,h1);
                *(__half2*)(g_rM + ro) = __halves2half2(m0h,m1h);
                *(__half2*)(g_rL + ro) = __halves2half2(l0,l1);
            }
        }
    }
}

__global__ void k_fin(float* __restrict__ out, int fo){
    if (fo && threadIdx.x==0){
        double t = g_loss;
        float enc = (float)(0.25 * t / ((double)Bn * (double)Dd));
        out[SC_OFF+0] = enc; out[SC_OFF+1] = enc; out[SC_OFF+2] = 0.f;
    }
}

extern "C" void kernel_launch(void* const* d_in, const int* in_sizes, int n_in,
                              void* d_out, int out_size) {
    const float* z  = (const float*)d_in[0];
    const float* cb = (const float*)d_in[1];
    const float* Wi = (const float*)d_in[2];
    const float* bi = (const float*)d_in[3];
    const float* Wo = (const float*)d_in[4];
    const float* bo = (const float*)d_in[5];
    float* out = (float*)d_out;
    const int fo = ((long)out_size > SC_OFF) ? 1 : 0;

    cudaFuncSetAttribute(k_gemm1, cudaFuncAttributeMaxDynamicSharedMemorySize, SMEMB);
    cudaFuncSetAttribute(k_dist,  cudaFuncAttributeMaxDynamicSharedMemorySize, D_SMEMB);
    cudaFuncSetAttribute(k_gemm3, cudaFuncAttributeMaxDynamicSharedMemorySize, SMEMB);

    k_prep_misc<<<NCB*Kk/256, 256>>>(cb);
    k_prep_z<<<(int)(((size_t)Bn*Cc)/256), 256>>>(z);
    k_prep_wi<<<(NCB*Cc*Dd)/256, 256>>>(Wi);
    k_prep_cb<<<(NCB*Kk*Dd)/256, 256>>>(cb);
    k_prep_wo<<<(NCB*Dd*Cc)/256, 256>>>(Wo);

    for (int i=0;i<NCB;i++){
        k_gemm1<<<dim3(512,4), 256, SMEMB>>>(bi + i*Dd, out, fo, i);
        k_zsq<<<Bn/8, 256>>>();
        k_dist<<<dim3(512,2), 256, D_SMEMB>>>(i);
        k_pick<<<Bn/8, 256>>>(cb, i);
        k_gather<<<Bn*4/256, 256>>>(cb, out, fo, i);
        k_gemm3<<<dim3(512,16), 256, SMEMB>>>(z, bo + i*Cc, out, i);
    }
    k_fin<<<1, 32>>>(out, fo);
}

// round 17
// speedup vs baseline: 2.0277x; 1.0376x over previous
#include <cuda_runtime.h>
#include <cuda_fp16.h>
#include <cstdint>

typedef unsigned long long ull;
constexpr int Bn=65536, Cc=1024, Dd=256, Kk=2048, NCB=4;
constexpr long SC_OFF=(long)Bn*Cc, CODE_OFF=SC_OFF+3, LAT_OFF=CODE_OFF+(long)Bn*NCB;
constexpr float SPL = 2048.f, SPLI = 1.f/2048.f;
constexpr float MARGIN = 1e-3f;

// gemm1 smem (double-buffered, 3-split)
constexpr uint32_t AHs=0, AMs=18432, ALs=36864;
constexpr uint32_t BHs=55296, BMs=64512, BLs=73728;
constexpr uint32_t BUFB=82944, SMEMB=2*BUFB;   // 165888

// dist smem: resident A (2 splits, 128 x 528B) + double-buffered B
constexpr uint32_t D_AH=0, D_AM=67584;
constexpr uint32_t D_B0=135168, D_BSZ=34816;
constexpr uint32_t D_SMEMB=204800;

// gemm3 v2 smem: resident ze H/M (512B-stride XOR swizzle) + streamed L + B
constexpr uint32_t G3_AH=0, G3_AM=65536;
constexpr uint32_t G3_AL=131072;               // 2 x 16384
constexpr uint32_t G3_B0=163840, G3_BB=24576;  // 2 x (3 x 8192)
constexpr uint32_t G3_SMEMB=212992;

// ---- static scratch ----
__device__ float g_resid[(size_t)Bn*Cc];
__device__ float g_ze[(size_t)Bn*Dd];
__device__ float g_zsq[Bn];
__device__ int   g_idx[Bn];
__device__ ull   g_cand[(size_t)Bn*128];
__device__ float g_c2[NCB*Kk];
__device__ double g_loss;
__device__ __align__(128) __half g_rH[(size_t)Bn*Cc];
__device__ __align__(128) __half g_rM[(size_t)Bn*Cc];
__device__ __align__(128) __half g_rL[(size_t)Bn*Cc];
__device__ __align__(128) __half g_zeH[(size_t)Bn*Dd];
__device__ __align__(128) __half g_zeM[(size_t)Bn*Dd];
__device__ __align__(128) __half g_zeL[(size_t)Bn*Dd];
__device__ __align__(128) __half g_WiH[(size_t)NCB*Dd*Cc];
__device__ __align__(128) __half g_WiM[(size_t)NCB*Dd*Cc];
__device__ __align__(128) __half g_WiL[(size_t)NCB*Dd*Cc];
__device__ __align__(128) __half g_cbH[(size_t)NCB*Kk*Dd];
__device__ __align__(128) __half g_cbM[(size_t)NCB*Kk*Dd];
__device__ __align__(128) __half g_cbL[(size_t)NCB*Kk*Dd];
__device__ __align__(128) __half g_WoH[(size_t)NCB*Cc*Dd];
__device__ __align__(128) __half g_WoM[(size_t)NCB*Cc*Dd];
__device__ __align__(128) __half g_WoL[(size_t)NCB*Cc*Dd];

// ---- helpers ----
__device__ __forceinline__ uint32_t smem_u32(const void* p){
    uint32_t a; asm("{ .reg .u64 t; cvta.to.shared.u64 t, %1; cvt.u32.u64 %0, t; }":"=r"(a):"l"(p)); return a;
}
__device__ __forceinline__ void cp16(uint32_t d, const void* s){
    asm volatile("cp.async.cg.shared.global [%0], [%1], 16;"::"r"(d),"l"(s));
}
__device__ __forceinline__ void ldsm4(uint32_t* r, uint32_t a){
    asm volatile("ldmatrix.sync.aligned.m8n8.x4.shared.b16 {%0,%1,%2,%3}, [%4];"
                 :"=r"(r[0]),"=r"(r[1]),"=r"(r[2]),"=r"(r[3]):"r"(a));
}
__device__ __forceinline__ void ldsm2(uint32_t& r0,uint32_t& r1, uint32_t a){
    asm volatile("ldmatrix.sync.aligned.m8n8.x2.shared.b16 {%0,%1}, [%2];"
                 :"=r"(r0),"=r"(r1):"r"(a));
}
__device__ __forceinline__ void mma16816(float* c, const uint32_t* a, uint32_t b0, uint32_t b1){
    asm volatile("mma.sync.aligned.m16n8k16.row.col.f32.f16.f16.f32 "
                 "{%0,%1,%2,%3},{%4,%5,%6,%7},{%8,%9},{%0,%1,%2,%3};"
                 :"+f"(c[0]),"+f"(c[1]),"+f"(c[2]),"+f"(c[3])
                 :"r"(a[0]),"r"(a[1]),"r"(a[2]),"r"(a[3]),"r"(b0),"r"(b1));
}
__device__ __forceinline__ void mma16816_z(float* d, const uint32_t* a, uint32_t b0, uint32_t b1){
    asm volatile("mma.sync.aligned.m16n8k16.row.col.f32.f16.f16.f32 "
                 "{%0,%1,%2,%3},{%4,%5,%6,%7},{%8,%9},{%10,%11,%12,%13};"
                 :"=f"(d[0]),"=f"(d[1]),"=f"(d[2]),"=f"(d[3])
                 :"r"(a[0]),"r"(a[1]),"r"(a[2]),"r"(a[3]),"r"(b0),"r"(b1),
                  "f"(0.f),"f"(0.f),"f"(0.f),"f"(0.f));
}
__device__ __forceinline__ void split3(float x, __half& h, __half& m, __half& l){
    h = __float2half_rn(x);
    float r1 = x - __half2float(h);
    m = __float2half_rn(r1 * SPL);
    float r2 = r1 - __half2float(m) * SPLI;
    l = __float2half_rn(r2 * (SPL * SPL));
}

struct Acc { float hh[2][4][4]; float x1[2][4][4]; float x2[2][4][4]; };
__device__ __forceinline__ float comb(const Acc& a, int mt,int nt,int ci){
    return fmaf(SPLI, fmaf(SPLI, a.x2[mt][nt][ci], a.x1[mt][nt][ci]), a.hh[mt][nt][ci]);
}

// ---- double-buffered mainloop (gemm1, 3-split, exact hh) ----
template<int KCH, bool EXACT>
__device__ __forceinline__ void gemm_run(
    const __half* __restrict__ Ah, const __half* __restrict__ Am, const __half* __restrict__ Al, int aK,
    const __half* __restrict__ Bh, const __half* __restrict__ Bm, const __half* __restrict__ Bl, int bK,
    uint32_t sb, int tid, int lane, int warpR0, int warpC0, Acc& ac)
{
    #pragma unroll
    for (int mt=0;mt<2;mt++)
        #pragma unroll
        for (int nt=0;nt<4;nt++)
            #pragma unroll
            for (int ci=0;ci<4;ci++){ ac.hh[mt][nt][ci]=0.f; ac.x1[mt][nt][ci]=0.f; ac.x2[mt][nt][ci]=0.f; }

    const uint32_t aro = (uint32_t)((warpR0 + (lane&15))*144 + (lane>>4)*16);
    const uint32_t bro = (uint32_t)((warpC0 + (lane&7))*144 + ((lane>>3)&1)*16);

    auto stage = [&](int c){
        uint32_t bufb = sb + (uint32_t)(c&1)*BUFB;
        const int kc = c*64;
        #pragma unroll
        for (int s=0;s<4;s++){
            int f = tid + 256*s, r = f>>3, j = f&7;
            uint32_t o = bufb + (uint32_t)(r*144 + j*16);
            const size_t src = (size_t)r*aK + kc + j*8;
            cp16(o + AHs, Ah + src);
            cp16(o + AMs, Am + src);
            cp16(o + ALs, Al + src);
        }
        #pragma unroll
        for (int s=0;s<2;s++){
            int f = tid + 256*s, r = f>>3, j = f&7;
            uint32_t o = bufb + (uint32_t)(r*144 + j*16);
            const size_t src = (size_t)r*bK + kc + j*8;
            cp16(o + BHs, Bh + src);
            cp16(o + BMs, Bm + src);
            cp16(o + BLs, Bl + src);
        }
        asm volatile("cp.async.commit_group;");
    };

    stage(0);
    for (int c=0;c<KCH;c++){
        if (c+1<KCH){ stage(c+1); asm volatile("cp.async.wait_group 1;"); }
        else asm volatile("cp.async.wait_group 0;");
        __syncthreads();
        uint32_t bufb = sb + (uint32_t)(c&1)*BUFB;
        #pragma unroll
        for (int kt=0;kt<4;kt++){
            uint32_t ah[2][4], am[2][4], al[2][4];
            #pragma unroll
            for (int mt=0;mt<2;mt++){
                ldsm4(ah[mt], bufb + AHs + aro + mt*2304 + kt*32);
                ldsm4(am[mt], bufb + AMs + aro + mt*2304 + kt*32);
                ldsm4(al[mt], bufb + ALs + aro + mt*2304 + kt*32);
            }
            #pragma unroll
            for (int nt=0;nt<4;nt++){
                uint32_t bh0,bh1,bm0,bm1,bl0,bl1;
                ldsm2(bh0,bh1, bufb + BHs + bro + nt*1152 + kt*32);
                ldsm2(bm0,bm1, bufb + BMs + bro + nt*1152 + kt*32);
                ldsm2(bl0,bl1, bufb + BLs + bro + nt*1152 + kt*32);
                #pragma unroll
                for (int mt=0;mt<2;mt++){
                    if (EXACT){
                        float t[4];
                        mma16816_z(t, ah[mt], bh0, bh1);
                        #pragma unroll
                        for (int ci=0;ci<4;ci++) ac.hh[mt][nt][ci] += t[ci];
                    } else {
                        mma16816(ac.hh[mt][nt], ah[mt], bh0, bh1);
                    }
                    mma16816(ac.x1[mt][nt], ah[mt], bm0, bm1);
                    mma16816(ac.x1[mt][nt], am[mt], bh0, bh1);
                    mma16816(ac.x2[mt][nt], am[mt], bm0, bm1);
                    mma16816(ac.x2[mt][nt], ah[mt], bl0, bl1);
                    mma16816(ac.x2[mt][nt], al[mt], bh0, bh1);
                }
            }
        }
        __syncthreads();
    }
}

// ---- prep ----
__global__ void k_prep_misc(const float* __restrict__ cb){
    int idx = blockIdx.x*blockDim.x + threadIdx.x;
    if (idx==0) g_loss = 0.0;
    const float* row = cb + (long)idx*Dd; float s=0.f;
    #pragma unroll 8
    for (int d=0; d<Dd; d++) s = fmaf(row[d], row[d], s);
    g_c2[idx] = s;
}
__global__ void k_prep_z(const float* __restrict__ z){
    size_t idx = (size_t)blockIdx.x*256 + threadIdx.x;
    __half h,m,l; split3(z[idx], h, m, l);
    g_rH[idx]=h; g_rM[idx]=m; g_rL[idx]=l;
}
__global__ void k_prep_wi(const float* __restrict__ Wi){
    int idx = blockIdx.x*256 + threadIdx.x;
    int n = idx & 255, k = (idx>>8) & 1023, i = idx>>18;
    __half h,m,l; split3(Wi[idx], h, m, l);
    size_t o = ((size_t)i*Dd + n)*Cc + k;
    g_WiH[o]=h; g_WiM[o]=m; g_WiL[o]=l;
}
__global__ void k_prep_cb(const float* __restrict__ cb){
    int idx = blockIdx.x*256 + threadIdx.x;
    __half h,m,l; split3(cb[idx], h, m, l);
    g_cbH[idx]=h; g_cbM[idx]=m; g_cbL[idx]=l;
}
__global__ void k_prep_wo(const float* __restrict__ Wo){
    int idx = blockIdx.x*256 + threadIdx.x;
    int n = idx & 1023, k = (idx>>10) & 255, i = idx>>18;
    __half h,m,l; split3(Wo[idx], h, m, l);
    size_t o = ((size_t)i*Cc + n)*Dd + k;
    g_WoH[o]=h; g_WoM[o]=m; g_WoL[o]=l;
}

// ---- GEMM1: z_e = resid @ Wi + bi ----
__global__ __launch_bounds__(256,1) void k_gemm1(const float* __restrict__ bi_i,
        float* __restrict__ out, int fo, int icb){
    extern __shared__ __align__(16) char sm[];
    uint32_t sb = smem_u32(sm);
    int tid=threadIdx.x, lane=tid&31, warp=tid>>5;
    int warpR0=(warp&3)*32, warpC0=(warp>>2)*32;
    long m0 = (long)blockIdx.x*128; int n0 = blockIdx.y*64;
    size_t ao = (size_t)m0*Cc;
    size_t bo_ = ((size_t)icb*Dd + n0)*Cc;
    Acc ac;
    gemm_run<16,true>(g_rH+ao, g_rM+ao, g_rL+ao, Cc,
                      g_WiH+bo_, g_WiM+bo_, g_WiL+bo_, Cc,
                      sb, tid, lane, warpR0, warpC0, ac);
    int tr = lane>>2, tc = (lane&3)*2;
    #pragma unroll
    for (int mt=0;mt<2;mt++)
    #pragma unroll
    for (int hv=0;hv<2;hv++){
        long gr = m0 + warpR0 + mt*16 + tr + 8*hv;
        #pragma unroll
        for (int nt=0;nt<4;nt++){
            int cg = n0 + warpC0 + nt*8 + tc;
            float v0 = comb(ac,mt,nt,hv*2+0) + bi_i[cg];
            float v1 = comb(ac,mt,nt,hv*2+1) + bi_i[cg+1];
            size_t zo = (size_t)gr*Dd + cg;
            *(float2*)(g_ze + zo) = make_float2(v0, v1);
            __half h0,mm0,l0,h1,mm1,l1;
            split3(v0,h0,mm0,l0); split3(v1,h1,mm1,l1);
            *(__half2*)(g_zeH + zo) = __halves2half2(h0,h1);
            *(__half2*)(g_zeM + zo) = __halves2half2(mm0,mm1);
            *(__half2*)(g_zeL + zo) = __halves2half2(l0,l1);
            if (fo){
                long o = LAT_OFF + gr*(long)(NCB*Dd) + (long)icb*Dd + cg;
                out[o] = v0; out[o+1] = v1;
            }
        }
    }
}

// ---- zsq ----
__global__ void k_zsq(){
    int warp = threadIdx.x>>5, lane = threadIdx.x&31;
    long row = (long)blockIdx.x*8 + warp;
    const float* p = g_ze + row*Dd;
    float s = 0.f;
    #pragma unroll
    for (int j=0;j<8;j++){ float v = p[lane + 32*j]; s = fmaf(v,v,s); }
    #pragma unroll
    for (int off=16; off; off>>=1) s += __shfl_down_sync(0xffffffffu, s, off);
    if (lane==0) g_zsq[row] = s;
}

// ---- DIST: resident A, internal ntile loop, double-buffered B ----
__global__ __launch_bounds__(256,1) void k_dist(int icb){
    extern __shared__ __align__(16) char sm[];
    uint32_t sb = smem_u32(sm);
    int tid=threadIdx.x, lane=tid&31, warp=tid>>5;
    int colg = warp>>2;
    int warpR0=(warp&3)*32, warpC0=colg*32;
    long m0 = (long)blockIdx.x*128;
    int ntbase = blockIdx.y*16;
    size_t ao = (size_t)m0*Dd;
    const __half* Ah = g_zeH + ao;
    const __half* Am = g_zeM + ao;
    const __half* BhAll = g_cbH + (size_t)icb*Kk*Dd;
    const __half* BmAll = g_cbM + (size_t)icb*Kk*Dd;

    #pragma unroll
    for (int s=0;s<16;s++){
        int f = tid + 256*s, r = f>>5, j = f&31;
        cp16(sb + D_AH + (uint32_t)(r*528 + j*16), Ah + (size_t)r*Dd + j*8);
        cp16(sb + D_AM + (uint32_t)(r*528 + j*16), Am + (size_t)r*Dd + j*8);
    }
    asm volatile("cp.async.commit_group;");

    auto stageB = [&](int ci){
        int nt = ntbase + (ci>>1);
        int kc = (ci&1)*128;
        uint32_t bb = sb + D_B0 + (uint32_t)(ci&1)*D_BSZ;
        size_t base = (size_t)(nt*64)*Dd + kc;
        #pragma unroll
        for (int s=0;s<4;s++){
            int f = tid + 256*s, r = f>>4, j = f&15;
            cp16(bb + (uint32_t)(r*272 + j*16), BhAll + base + (size_t)r*Dd + j*8);
            cp16(bb + 17408u + (uint32_t)(r*272 + j*16), BmAll + base + (size_t)r*Dd + j*8);
        }
        asm volatile("cp.async.commit_group;");
    };
    stageB(0);

    int tr = lane>>2, tc = (lane&3)*2;
    float zsv[2][2];
    #pragma unroll
    for (int mt=0;mt<2;mt++)
        #pragma unroll
        for (int hv=0;hv<2;hv++)
            zsv[mt][hv] = g_zsq[m0 + warpR0 + mt*16 + tr + 8*hv];
    const uint32_t aro = (uint32_t)((warpR0 + (lane&15))*528 + (lane>>4)*16);
    const uint32_t bro = (uint32_t)((warpC0 + (lane&7))*272 + ((lane>>3)&1)*16);
    const float* c2p = g_c2 + icb*Kk;

    for (int nt=0; nt<16; nt++){
        float hh[2][4][4], x1[2][4][4];
        #pragma unroll
        for (int mt=0;mt<2;mt++)
            #pragma unroll
            for (int n2=0;n2<4;n2++)
                #pragma unroll
                for (int ci=0;ci<4;ci++){ hh[mt][n2][ci]=0.f; x1[mt][n2][ci]=0.f; }
        for (int c=0;c<2;c++){
            int ci = nt*2 + c;
            if (ci+1 < 32){ stageB(ci+1); asm volatile("cp.async.wait_group 1;"); }
            else asm volatile("cp.async.wait_group 0;");
            __syncthreads();
            uint32_t bb = sb + D_B0 + (uint32_t)(ci&1)*D_BSZ;
            #pragma unroll
            for (int kt=0;kt<8;kt++){
                int ktg = c*8 + kt;
                uint32_t ah[2][4], am[2][4];
                #pragma unroll
                for (int mt=0;mt<2;mt++){
                    ldsm4(ah[mt], sb + D_AH + aro + mt*8448 + ktg*32);
                    ldsm4(am[mt], sb + D_AM + aro + mt*8448 + ktg*32);
                }
                #pragma unroll
                for (int n2=0;n2<4;n2++){
                    uint32_t bh0,bh1,bm0,bm1;
                    ldsm2(bh0,bh1, bb + bro + n2*2176 + kt*32);
                    ldsm2(bm0,bm1, bb + 17408u + bro + n2*2176 + kt*32);
                    #pragma unroll
                    for (int mt=0;mt<2;mt++){
                        mma16816(hh[mt][n2], ah[mt], bh0, bh1);
                        mma16816(x1[mt][n2], ah[mt], bm0, bm1);
                        mma16816(x1[mt][n2], am[mt], bh0, bh1);
                    }
                }
            }
            __syncthreads();
        }
        int code_b = (ntbase + nt)*64;
        const int slot0 = ((ntbase + nt)*2 + colg)*2;
        #pragma unroll
        for (int mt=0;mt<2;mt++)
        #pragma unroll
        for (int hv=0;hv<2;hv++){
            long gr = m0 + warpR0 + mt*16 + tr + 8*hv;
            float zs = zsv[mt][hv];
            float dvv[8]; int cgg[8];
            #pragma unroll
            for (int n2=0;n2<4;n2++)
                #pragma unroll
                for (int jj=0;jj<2;jj++){
                    int q = n2*2+jj;
                    cgg[q] = code_b + warpC0 + n2*8 + tc + jj;
                    float dot = fmaf(SPLI, x1[mt][n2][hv*2+jj], hh[mt][n2][hv*2+jj]);
                    dvv[q] = (zs - 2.0f*dot) + c2p[cgg[q]];
                }
            float m1v = dvv[0]; int m1i = cgg[0];
            #pragma unroll
            for (int q=1;q<8;q++) if (dvv[q] < m1v || (dvv[q]==m1v && cgg[q]<m1i)){ m1v=dvv[q]; m1i=cgg[q]; }
            #pragma unroll
            for (int off=1; off<4; off<<=1){
                float ov = __shfl_xor_sync(0xffffffffu, m1v, off);
                int   oi = __shfl_xor_sync(0xffffffffu, m1i, off);
                if (ov < m1v || (ov == m1v && oi < m1i)){ m1v=ov; m1i=oi; }
            }
            float m2v = __int_as_float(0x7f800000); int m2i = 0x7fffffff;
            #pragma unroll
            for (int q=0;q<8;q++)
                if (cgg[q]!=m1i && (dvv[q] < m2v || (dvv[q]==m2v && cgg[q]<m2i))){ m2v=dvv[q]; m2i=cgg[q]; }
            #pragma unroll
            for (int off=1; off<4; off<<=1){
                float ov = __shfl_xor_sync(0xffffffffu, m2v, off);
                int   oi = __shfl_xor_sync(0xffffffffu, m2i, off);
                if (ov < m2v || (ov == m2v && oi < m2i)){ m2v=ov; m2i=oi; }
            }
            if ((lane&3)==0){
                g_cand[gr*128 + slot0 + 0] = ((ull)__float_as_uint(m1v)<<32) | (unsigned)m1i;
                g_cand[gr*128 + slot0 + 1] = ((ull)__float_as_uint(m2v)<<32) | (unsigned)m2i;
            }
        }
    }
}

// ---- PICK ----
__global__ __launch_bounds__(256) void k_pick(const float* __restrict__ cb, int icb){
    int warp = threadIdx.x>>5, lane = threadIdx.x&31;
    long row = (long)blockIdx.x*8 + warp;
    ull cc[4];
    #pragma unroll
    for (int s=0;s<4;s++) cc[s] = g_cand[row*128 + lane*4 + s];
    float mv = __int_as_float(0x7f800000);
    #pragma unroll
    for (int s=0;s<4;s++) mv = fminf(mv, __uint_as_float((uint32_t)(cc[s]>>32)));
    #pragma unroll
    for (int off=16; off; off>>=1) mv = fminf(mv, __shfl_xor_sync(0xffffffffu, mv, off));
    float thr = mv + MARGIN;
    const float* zep = g_ze + row*Dd;
    float zs = g_zsq[row];
    const float* c2p = g_c2 + icb*Kk;
    float bde = __int_as_float(0x7f800000); int bcg = 0x7fffffff;
    #pragma unroll
    for (int s=0;s<4;s++){
        float dv = __uint_as_float((uint32_t)(cc[s]>>32));
        int cg = (int)(cc[s] & 0xffffffffu);
        if (dv <= thr){
            const float* cbp = cb + ((long)icb*Kk + cg)*Dd;
            float dot = 0.f;
            #pragma unroll 8
            for (int j=0;j<64;j++){
                float4 a = *(const float4*)(zep + 4*j);
                float4 b = __ldg((const float4*)(cbp + 4*j));
                dot = fmaf(a.x,b.x,dot); dot = fmaf(a.y,b.y,dot);
                dot = fmaf(a.z,b.z,dot); dot = fmaf(a.w,b.w,dot);
            }
            float de = (zs - 2.0f*dot) + c2p[cg];
            if (de < bde || (de == bde && cg < bcg)){ bde = de; bcg = cg; }
        }
    }
    #pragma unroll
    for (int off=16; off; off>>=1){
        float od = __shfl_xor_sync(0xffffffffu, bde, off);
        int   oc = __shfl_xor_sync(0xffffffffu, bcg, off);
        if (od < bde || (od == bde && oc < bcg)){ bde = od; bcg = oc; }
    }
    if (lane==0) g_idx[row] = bcg;
}

// ---- GATHER ----
__global__ __launch_bounds__(256) void k_gather(const float* __restrict__ cb,
        float* __restrict__ out, int fo, int icb){
    int tid = threadIdx.x, lane = tid&31, warp = tid>>5;
    long gid = (long)blockIdx.x*256 + tid;
    long row = gid >> 2; int seg = (int)(gid & 3) * 64;
    int code = g_idx[row];
    const float* ep = cb + ((long)icb*Kk + code)*Dd + seg;
    float* zp = g_ze + row*Dd + seg;
    size_t zo = (size_t)row*Dd + seg;
    float lp = 0.f;
    #pragma unroll
    for (int j=0;j<16;j++){
        float4 ze4 = *(const float4*)(zp + 4*j);
        float4 e4  = *(const float4*)(ep + 4*j);
        float d0 = ze4.x-e4.x, d1 = ze4.y-e4.y, d2 = ze4.z-e4.z, d3 = ze4.w-e4.w;
        lp = fmaf(d0,d0,fmaf(d1,d1,fmaf(d2,d2,fmaf(d3,d3,lp))));
        float q0 = ze4.x+(e4.x-ze4.x), q1 = ze4.y+(e4.y-ze4.y);
        float q2 = ze4.z+(e4.z-ze4.z), q3 = ze4.w+(e4.w-ze4.w);
        *(float4*)(zp + 4*j) = make_float4(q0,q1,q2,q3);
        __half h0,m0,l0,h1,m1,l1,h2,m2,l2,h3,m3,l3;
        split3(q0,h0,m0,l0); split3(q1,h1,m1,l1);
        split3(q2,h2,m2,l2); split3(q3,h3,m3,l3);
        *(__half2*)(g_zeH + zo + 4*j)     = __halves2half2(h0,h1);
        *(__half2*)(g_zeH + zo + 4*j + 2) = __halves2half2(h2,h3);
        *(__half2*)(g_zeM + zo + 4*j)     = __halves2half2(m0,m1);
        *(__half2*)(g_zeM + zo + 4*j + 2) = __halves2half2(m2,m3);
        *(__half2*)(g_zeL + zo + 4*j)     = __halves2half2(l0,l1);
        *(__half2*)(g_zeL + zo + 4*j + 2) = __halves2half2(l2,l3);
    }
    if (fo && (gid&3)==0) out[CODE_OFF + row*NCB + icb] = (float)code;
    #pragma unroll
    for (int off=16; off; off>>=1) lp += __shfl_down_sync(0xffffffffu, lp, off);
    __shared__ float wr[8];
    if (lane==0) wr[warp] = lp;
    __syncthreads();
    if (tid==0){ float s=0.f; for (int w=0;w<8;w++) s += wr[w]; atomicAdd(&g_loss, (double)s); }
}

// ---- GEMM3 v2: resident ze H/M (XOR swizzle), streamed L + Wo; 8 ntiles/CTA ----
__global__ __launch_bounds__(256,1) void k_gemm3(const float* __restrict__ z,
        const float* __restrict__ bo_i, float* __restrict__ out, int icb){
    extern __shared__ __align__(16) char sm[];
    uint32_t sb = smem_u32(sm);
    int tid=threadIdx.x, lane=tid&31, warp=tid>>5;
    int warpR0=(warp&3)*32, warpC0=(warp>>2)*32;
    long m0 = (long)blockIdx.x*128;
    int ntb = blockIdx.y*8;                 // 8 ntiles per CTA
    size_t ao = (size_t)m0*Dd;
    const __half* Ah = g_zeH + ao;
    const __half* Am = g_zeM + ao;
    const __half* Al = g_zeL + ao;
    const __half* BhAll = g_WoH + (size_t)icb*Cc*Dd;
    const __half* BmAll = g_WoM + (size_t)icb*Cc*Dd;
    const __half* BlAll = g_WoL + (size_t)icb*Cc*Dd;

    // resident A H/M: 128 rows x 512B, chunk-swizzle c ^= (r&7)
    #pragma unroll
    for (int s=0;s<16;s++){
        int f = tid + 256*s, r = f>>5, c = f&31;
        uint32_t d = (uint32_t)(r*512 + ((c&24)|((c^r)&7))*16);
        cp16(sb + G3_AH + d, Ah + (size_t)r*Dd + c*8);
        cp16(sb + G3_AM + d, Am + (size_t)r*Dd + c*8);
    }
    asm volatile("cp.async.commit_group;");

    auto stageQ = [&](int q){                // q = local_nt*4 + c
        int nt = ntb + (q>>2), c = q&3, b = q&1;
        uint32_t alb = sb + G3_AL + (uint32_t)b*16384;
        #pragma unroll
        for (int s=0;s<4;s++){
            int f = tid + 256*s, r = f>>3, j = f&7;
            cp16(alb + (uint32_t)(r*128 + ((j^(r&7)))*16), Al + (size_t)r*Dd + c*64 + j*8);
        }
        uint32_t bb = sb + G3_B0 + (uint32_t)b*G3_BB;
        size_t base = (size_t)(nt*64)*Dd + c*64;
        #pragma unroll
        for (int s=0;s<2;s++){
            int f = tid + 256*s, r = f>>3, j = f&7;
            uint32_t d = (uint32_t)(r*128 + ((j^(r&7)))*16);
            size_t src = base + (size_t)r*Dd + j*8;
            cp16(bb + d,          BhAll + src);
            cp16(bb + 8192u + d,  BmAll + src);
            cp16(bb + 16384u + d, BlAll + src);
        }
        asm volatile("cp.async.commit_group;");
    };
    stageQ(0);

    // precomputed ldsm offsets
    int hb = lane>>4;
    int rA0 = warpR0 + (lane&15); int rx = rA0 & 7;     // mt*16 keeps r&7
    uint32_t aA[2], aAL[2];
    #pragma unroll
    for (int mt=0;mt<2;mt++){ aA[mt] = (uint32_t)((rA0+mt*16)*512); aAL[mt] = (uint32_t)((rA0+mt*16)*128); }
    uint32_t xk[4];
    #pragma unroll
    for (int kt=0;kt<4;kt++) xk[kt] = (uint32_t)(((kt*2+hb)^rx)*16);
    int hbB = (lane>>3)&1;
    int rB0 = warpC0 + (lane&7); int rbx = rB0&7;       // n2*8 keeps r&7
    uint32_t xkb[4];
    #pragma unroll
    for (int kt=0;kt<4;kt++) xkb[kt] = (uint32_t)(((kt*2+hbB)^rbx)*16);

    int tr = lane>>2, tc = (lane&3)*2;
    const float* rsrc = (icb ? g_resid : z);
    const int last = (icb == NCB-1);

    float hh[2][4][4], x1[2][4][4], x2[2][4][4];
    for (int q=0;q<32;q++){
        int c = q&3, b = q&1;
        if (c==0){
            #pragma unroll
            for (int mt=0;mt<2;mt++)
                #pragma unroll
                for (int n2=0;n2<4;n2++)
                    #pragma unroll
                    for (int ci=0;ci<4;ci++){ hh[mt][n2][ci]=0.f; x1[mt][n2][ci]=0.f; x2[mt][n2][ci]=0.f; }
        }
        if (q+1<32){ stageQ(q+1); asm volatile("cp.async.wait_group 1;"); }
        else asm volatile("cp.async.wait_group 0;");
        __syncthreads();
        uint32_t alb = sb + G3_AL + (uint32_t)b*16384;
        uint32_t bb  = sb + G3_B0 + (uint32_t)b*G3_BB;
        #pragma unroll
        for (int kt=0;kt<4;kt++){
            uint32_t ah[2][4], am[2][4], al[2][4];
            #pragma unroll
            for (int mt=0;mt<2;mt++){
                ldsm4(ah[mt], sb + G3_AH + aA[mt] + (uint32_t)(c*128) + xk[kt]);
                ldsm4(am[mt], sb + G3_AM + aA[mt] + (uint32_t)(c*128) + xk[kt]);
                ldsm4(al[mt], alb + aAL[mt] + xk[kt]);
            }
            #pragma unroll
            for (int n2=0;n2<4;n2++){
                uint32_t bh0,bh1,bm0,bm1,bl0,bl1;
                uint32_t brb = (uint32_t)((rB0 + n2*8)*128) + xkb[kt];
                ldsm2(bh0,bh1, bb + brb);
                ldsm2(bm0,bm1, bb + 8192u + brb);
                ldsm2(bl0,bl1, bb + 16384u + brb);
                #pragma unroll
                for (int mt=0;mt<2;mt++){
                    float t[4];
                    mma16816_z(t, ah[mt], bh0, bh1);
                    #pragma unroll
                    for (int ci=0;ci<4;ci++) hh[mt][n2][ci] += t[ci];
                    mma16816(x1[mt][n2], ah[mt], bm0, bm1);
                    mma16816(x1[mt][n2], am[mt], bh0, bh1);
                    mma16816(x2[mt][n2], am[mt], bm0, bm1);
                    mma16816(x2[mt][n2], ah[mt], bl0, bl1);
                    mma16816(x2[mt][n2], al[mt], bh0, bh1);
                }
            }
        }
        __syncthreads();
        if (c==3){
            int n0 = (ntb + (q>>2))*64;
            #pragma unroll
            for (int mt=0;mt<2;mt++)
            #pragma unroll
            for (int hv=0;hv<2;hv++){
                long gr = m0 + warpR0 + mt*16 + tr + 8*hv;
                #pragma unroll
                for (int n2=0;n2<4;n2++){
                    int cg = n0 + warpC0 + n2*8 + tc;
                    float c0 = fmaf(SPLI, fmaf(SPLI, x2[mt][n2][hv*2+0], x1[mt][n2][hv*2+0]), hh[mt][n2][hv*2+0]);
                    float c1 = fmaf(SPLI, fmaf(SPLI, x2[mt][n2][hv*2+1], x1[mt][n2][hv*2+1]), hh[mt][n2][hv*2+1]);
                    float v0 = c0 + bo_i[cg];
                    float v1 = c1 + bo_i[cg+1];
                    size_t ro = (size_t)gr*Cc + cg;
                    float2 rv = *(const float2*)(rsrc + ro);
                    float nr0 = rv.x - v0, nr1 = rv.y - v1;
                    if (last){
                        float2 zz = *(const float2*)(z + ro);
                        *(float2*)(out + ro) = make_float2(zz.x - nr0, zz.y - nr1);
                    } else {
                        *(float2*)(g_resid + ro) = make_float2(nr0, nr1);
                        __half h0,m0h,l0,h1,m1h,l1;
                        split3(nr0,h0,m0h,l0); split3(nr1,h1,m1h,l1);
                        *(__half2*)(g_rH + ro) = __halves2half2(h0,h1);
                        *(__half2*)(g_rM + ro) = __halves2half2(m0h,m1h);
                        *(__half2*)(g_rL + ro) = __halves2half2(l0,l1);
                    }
                }
            }
        }
    }
}

__global__ void k_fin(float* __restrict__ out, int fo){
    if (fo && threadIdx.x==0){
        double t = g_loss;
        float enc = (float)(0.25 * t / ((double)Bn * (double)Dd));
        out[SC_OFF+0] = enc; out[SC_OFF+1] = enc; out[SC_OFF+2] = 0.f;
    }
}

extern "C" void kernel_launch(void* const* d_in, const int* in_sizes, int n_in,
                              void* d_out, int out_size) {
    const float* z  = (const float*)d_in[0];
    const float* cb = (const float*)d_in[1];
    const float* Wi = (const float*)d_in[2];
    const float* bi = (const float*)d_in[3];
    const float* Wo = (const float*)d_in[4];
    const float* bo = (const float*)d_in[5];
    float* out = (float*)d_out;
    const int fo = ((long)out_size > SC_OFF) ? 1 : 0;

    cudaFuncSetAttribute(k_gemm1, cudaFuncAttributeMaxDynamicSharedMemorySize, SMEMB);
    cudaFuncSetAttribute(k_dist,  cudaFuncAttributeMaxDynamicSharedMemorySize, D_SMEMB);
    cudaFuncSetAttribute(k_gemm3, cudaFuncAttributeMaxDynamicSharedMemorySize, G3_SMEMB);

    k_prep_misc<<<NCB*Kk/256, 256>>>(cb);
    k_prep_z<<<(int)(((size_t)Bn*Cc)/256), 256>>>(z);
    k_prep_wi<<<(NCB*Cc*Dd)/256, 256>>>(Wi);
    k_prep_cb<<<(NCB*Kk*Dd)/256, 256>>>(cb);
    k_prep_wo<<<(NCB*Dd*Cc)/256, 256>>>(Wo);

    for (int i=0;i<NCB;i++){
        k_gemm1<<<dim3(512,4), 256, SMEMB>>>(bi + i*Dd, out, fo, i);
        k_zsq<<<Bn/8, 256>>>();
        k_dist<<<dim3(512,2), 256, D_SMEMB>>>(i);
        k_pick<<<Bn/8, 256>>>(cb, i);
        k_gather<<<Bn*4/256, 256>>>(cb, out, fo, i);
        k_gemm3<<<dim3(512,2), 256, G3_SMEMB>>>(z, bo + i*Cc, out, i);
    }
    k_fin<<<1, 32>>>(out, fo);
}